// round 4
// baseline (speedup 1.0000x reference)
#include <cuda_runtime.h>
#include <math.h>

#define S_LEN 256
#define BATCH 64
#define VOCAB 10000
#define EDIM  512
#define HDIM  1024

typedef unsigned long long u64;

// ---------------- packed fp32x2 helpers (sm_103a FFMA2) ----------------
__device__ __forceinline__ u64 pack2(float lo, float hi) {
    u64 r; asm("mov.b64 %0,{%1,%2};" : "=l"(r) : "f"(lo), "f"(hi)); return r;
}
__device__ __forceinline__ float2 unpack2(u64 v) {
    float2 f; asm("mov.b64 {%0,%1},%2;" : "=f"(f.x), "=f"(f.y) : "l"(v)); return f;
}
__device__ __forceinline__ void ffma2(u64 &c, u64 a, u64 b) {
    asm("fma.rn.f32x2 %0,%1,%2,%0;" : "+l"(c) : "l"(a), "l"(b));
}

// ---------------- scratch (static device memory; no allocations) -------
__device__ float g_W0X[512 * 3072];
__device__ float g_W0A[1024 * 2048];
__device__ float g_W0B[1024 * 1024];
__device__ float g_W1A[2048 * 3072];
__device__ float g_W1B[1024 * 1024];
__device__ float g_bias[6 * 1024];
__device__ float g_xpre[(size_t)16384 * 3072];
__device__ float g_top[(size_t)16384 * 1024];
__device__ float g_cat[64 * 2048];
__device__ float g_rh[64 * 1024];
__device__ float g_z[64 * 1024];
__device__ float g_xh1[64 * 1024];
__device__ float g_part[2359296];          // split-K partials (max 12*64*3072)
__device__ int   g_cnt1[32] = {};          // leaf counters (8 CTAs each)
__device__ int   g_root = 0;
__device__ int   g_gen = 0;

// ---------------- two-level grid barrier (148 co-resident CTAs) --------
__device__ __forceinline__ void grid_bar(int &gen) {
    __threadfence();
    __syncthreads();
    if (threadIdx.x == 0) {
        int g = blockIdx.x >> 3;
        int ngrp = ((int)gridDim.x + 7) >> 3;
        int gsz = min(8, (int)gridDim.x - (g << 3));
        if (atomicAdd(&g_cnt1[g], 1) == gsz - 1) {
            atomicExch(&g_cnt1[g], 0);
            if (atomicAdd(&g_root, 1) == ngrp - 1) {
                atomicExch(&g_root, 0);
                __threadfence();
                atomicAdd(&g_gen, 1);
            }
        }
        volatile int* vg = &g_gen;
        while (*vg - gen <= 0) { }
        __threadfence();
    }
    gen++;
    __syncthreads();
}

// ---------------- weight repack + state init ---------------------------
__global__ void k_prep(const float* __restrict__ hidden,
                       const float* __restrict__ Wr0, const float* __restrict__ Wz0,
                       const float* __restrict__ Wh0,
                       const float* __restrict__ Wr1, const float* __restrict__ Wz1,
                       const float* __restrict__ Wh1,
                       const float* __restrict__ br0, const float* __restrict__ bz0,
                       const float* __restrict__ bh0,
                       const float* __restrict__ br1, const float* __restrict__ bz1,
                       const float* __restrict__ bh1) {
    int i = blockIdx.x * blockDim.x + threadIdx.x;
    if (i < 512 * 3072) {
        int k = i / 3072, n = i % 3072;
        float v = (n < 1024) ? Wr0[k * 1024 + n]
                : (n < 2048) ? Wz0[k * 1024 + n - 1024]
                             : Wh0[k * 1024 + n - 2048];
        g_W0X[i] = v;
    }
    if (i < 1024 * 2048) {
        int k = i / 2048, n = i % 2048;
        g_W0A[i] = (n < 1024) ? Wr0[(512 + k) * 1024 + n]
                              : Wz0[(512 + k) * 1024 + n - 1024];
    }
    if (i < 1024 * 1024) {
        int k = i >> 10, n = i & 1023;
        g_W0B[i] = Wh0[(512 + k) * 1024 + n];
        g_W1B[i] = Wh1[(1024 + k) * 1024 + n];
    }
    if (i < 2048 * 3072) {
        int k = i / 3072, n = i % 3072;
        float v;
        if (n < 1024)      v = Wr1[k * 1024 + n];
        else if (n < 2048) v = Wz1[k * 1024 + n - 1024];
        else               v = (k < 1024) ? Wh1[k * 1024 + (n - 2048)] : 0.f;
        g_W1A[i] = v;
    }
    if (i < 1024) {
        g_bias[i]        = br0[i]; g_bias[1024 + i] = bz0[i]; g_bias[2048 + i] = bh0[i];
        g_bias[3072 + i] = br1[i]; g_bias[4096 + i] = bz1[i]; g_bias[5120 + i] = bh1[i];
    }
    if (i < 64 * 2048) {
        int b = i >> 11, j = i & 2047;
        g_cat[i] = (j < 1024) ? hidden[b * 1024 + j]
                              : hidden[65536 + b * 1024 + (j - 1024)];
    }
}

// ---------------- 64x256 tile GEMM core (FFMA2, vector smem) -----------
// 256 threads as 16(tx) x 16(ty); per-thread 4 rows x 16 cols (acc[4][8] u64)
template <bool CGA, bool GATHER>
__device__ __forceinline__ void mm_core(
    const float* __restrict__ A, int lda,
    const float* __restrict__ Emb, const int* __restrict__ tokens, int m0,
    const float* __restrict__ B, int ldb, int n0, int Nvalid,
    int kbeg, int kend, u64 acc[4][8]) {
    __shared__ __align__(16) float As[32][68];
    __shared__ __align__(16) float Bs[32][256];
    __shared__ int s_tok[64];
    const int tid = threadIdx.x;
    if (GATHER) {
        if (tid < 64) s_tok[tid] = tokens[m0 + tid];
        __syncthreads();
    }
    const int tx = tid & 15, ty = tid >> 4;
    const bool full = (n0 + 256 <= Nvalid);
    for (int k0 = kbeg; k0 < kend; k0 += 32) {
        // A fill: 64 rows x 32 k, as float4 along k (512 float4 slots)
#pragma unroll
        for (int i = 0; i < 2; i++) {
            int slot = tid + i * 256;
            int mm = slot >> 3, kk = (slot & 7) * 4;
            int kg = k0 + kk;
            float4 v = make_float4(0.f, 0.f, 0.f, 0.f);
            if (kg < kend) {
                const float* p;
                if (GATHER) p = &Emb[(size_t)s_tok[mm] * EDIM + kg];
                else        p = &A[(size_t)(m0 + mm) * lda + kg];
                v = CGA ? __ldcg((const float4*)p) : *(const float4*)p;
            }
            As[kk][mm] = v.x; As[kk + 1][mm] = v.y;
            As[kk + 2][mm] = v.z; As[kk + 3][mm] = v.w;
        }
        // B fill: 32 k x 256 n as float4 (2048 slots)
#pragma unroll
        for (int i = 0; i < 8; i++) {
            int slot = tid + i * 256;
            int kk = slot >> 6, nn = (slot & 63) * 4;
            int kg = k0 + kk, ng = n0 + nn;
            float4 v = make_float4(0.f, 0.f, 0.f, 0.f);
            if (kg < kend) {
                if (full) {
                    v = *(const float4*)&B[(size_t)kg * ldb + ng];
                } else {
                    if (ng     < Nvalid) v.x = B[(size_t)kg * ldb + ng];
                    if (ng + 1 < Nvalid) v.y = B[(size_t)kg * ldb + ng + 1];
                    if (ng + 2 < Nvalid) v.z = B[(size_t)kg * ldb + ng + 2];
                    if (ng + 3 < Nvalid) v.w = B[(size_t)kg * ldb + ng + 3];
                }
            }
            *(float4*)&Bs[kk][nn] = v;
        }
        __syncthreads();
#pragma unroll 4
        for (int k = 0; k < 32; k++) {
            float4 a4 = *(const float4*)&As[k][ty * 4];
            u64 a2[4];
            a2[0] = pack2(a4.x, a4.x); a2[1] = pack2(a4.y, a4.y);
            a2[2] = pack2(a4.z, a4.z); a2[3] = pack2(a4.w, a4.w);
            ulonglong2 b0 = *(const ulonglong2*)&Bs[k][tx * 16];
            ulonglong2 b1 = *(const ulonglong2*)&Bs[k][tx * 16 + 4];
            ulonglong2 b2 = *(const ulonglong2*)&Bs[k][tx * 16 + 8];
            ulonglong2 b3 = *(const ulonglong2*)&Bs[k][tx * 16 + 12];
#pragma unroll
            for (int i = 0; i < 4; i++) {
                ffma2(acc[i][0], a2[i], b0.x); ffma2(acc[i][1], a2[i], b0.y);
                ffma2(acc[i][2], a2[i], b1.x); ffma2(acc[i][3], a2[i], b1.y);
                ffma2(acc[i][4], a2[i], b2.x); ffma2(acc[i][5], a2[i], b2.y);
                ffma2(acc[i][6], a2[i], b3.x); ffma2(acc[i][7], a2[i], b3.y);
            }
        }
        __syncthreads();
    }
}

// ---------------- layer0 x-side precompute (gathered GEMM) -------------
__global__ __launch_bounds__(256) void k_embed(const int* __restrict__ inputs,
                                               const float* __restrict__ Emb) {
    u64 acc[4][8] = {};
    int n0 = blockIdx.x * 256, m0 = blockIdx.y * 64;
    mm_core<false, true>(nullptr, 0, Emb, inputs, m0, g_W0X, 3072, n0, 3072, 0, 512, acc);
    int tx = threadIdx.x & 15, ty = threadIdx.x >> 4;
#pragma unroll
    for (int i = 0; i < 4; i++) {
        size_t row = m0 + ty * 4 + i;
        float* dst = &g_xpre[row * 3072 + n0 + tx * 16];
#pragma unroll
        for (int q = 0; q < 4; q++) {
            float2 p0 = unpack2(acc[i][2 * q]);
            float2 p1 = unpack2(acc[i][2 * q + 1]);
            *(float4*)(dst + 4 * q) = make_float4(p0.x, p0.y, p1.x, p1.y);
        }
    }
}

// ---------------- split-K partial GEMM inside persistent kernel --------
__device__ __forceinline__ void phase_gemm(const float* A, int lda,
                                           const float* B, int ldb, int N,
                                           int ntile, int sp, int kbeg, int kend) {
    u64 acc[4][8] = {};
    int n0 = ntile * 256;
    mm_core<true, false>(A, lda, nullptr, nullptr, 0, B, ldb, n0, N, kbeg, kend, acc);
    float* part = g_part + (size_t)sp * 64 * N;
    int tx = threadIdx.x & 15, ty = threadIdx.x >> 4;
#pragma unroll
    for (int i = 0; i < 4; i++) {
        int r = ty * 4 + i;
        float* dst = &part[(size_t)r * N + n0 + tx * 16];
#pragma unroll
        for (int q = 0; q < 4; q++) {
            float2 p0 = unpack2(acc[i][2 * q]);
            float2 p1 = unpack2(acc[i][2 * q + 1]);
            *(float4*)(dst + 4 * q) = make_float4(p0.x, p0.y, p1.x, p1.y);
        }
    }
}

__device__ __forceinline__ float sigm(float x) { return 1.f / (1.f + expf(-x)); }

// ---------------- persistent recurrent kernel --------------------------
__global__ __launch_bounds__(256) void k_rec_persist() {
    const int cta = blockIdx.x, tid = threadIdx.x;
    const int gtid = cta * 256 + tid;
    const int nthr = (int)gridDim.x * 256;
    int gen = *(volatile int*)&g_gen;

    for (int s = 0; s < S_LEN; s++) {
        const int sb = s * BATCH;
        // ---- Phase A: h0 @ [Wr0_h|Wz0_h]  (N=2048: 8 ntiles x 16 splits) ----
        if (cta < 128) {
            int nt = cta & 7, sp = cta >> 3;
            phase_gemm(g_cat, 2048, g_W0A, 2048, 2048, nt, sp, sp * 64, sp * 64 + 64);
        }
        grid_bar(gen);
        for (int e = gtid; e < 131072; e += nthr) {
            int r = e >> 11, n = e & 2047;
            float sum = 0.f;
#pragma unroll
            for (int sp = 0; sp < 16; sp++) sum += __ldcg(&g_part[sp * 131072 + e]);
            if (n < 1024) {
                float pre = sum + g_xpre[(size_t)(sb + r) * 3072 + n] + g_bias[n];
                g_rh[r * 1024 + n] = sigm(pre) * __ldcg(&g_cat[r * 2048 + n]);
            } else {
                int j = n - 1024;
                float pre = sum + g_xpre[(size_t)(sb + r) * 3072 + 1024 + j] + g_bias[1024 + j];
                g_z[r * 1024 + j] = sigm(pre);
            }
        }
        grid_bar(gen);
        // ---- Phase B: (r*h0) @ Wh0_h  (N=1024: 4 ntiles x 32 splits) ----
        if (cta < 128) {
            int nt = cta & 3, sp = cta >> 2;
            phase_gemm(g_rh, 1024, g_W0B, 1024, 1024, nt, sp, sp * 32, sp * 32 + 32);
        }
        grid_bar(gen);
        for (int e = gtid; e < 65536; e += nthr) {
            int r = e >> 10, n = e & 1023;
            float sum = 0.f;
#pragma unroll
            for (int sp = 0; sp < 32; sp++) sum += __ldcg(&g_part[sp * 65536 + e]);
            float pre = sum + g_xpre[(size_t)(sb + r) * 3072 + 2048 + n] + g_bias[2048 + n];
            float hh = tanhf(pre);
            float z = __ldcg(&g_z[e]);
            float h = __ldcg(&g_cat[r * 2048 + n]);
            g_cat[r * 2048 + n] = (1.f - z) * h + z * hh;
        }
        grid_bar(gen);
        // ---- Phase C: [h0new|h1] @ [Wr1|Wz1|Wh1_x]  (N=3072: 12 x 12) ----
        if (cta < 144) {
            int nt = cta % 12, sp = cta / 12;
            int kb = sp * 176, ke = min(2048, kb + 176);
            phase_gemm(g_cat, 2048, g_W1A, 3072, 3072, nt, sp, kb, ke);
        }
        grid_bar(gen);
        for (int e = gtid; e < 196608; e += nthr) {
            int r = e / 3072, n = e - r * 3072;
            float sum = 0.f;
#pragma unroll
            for (int sp = 0; sp < 12; sp++) sum += __ldcg(&g_part[sp * 196608 + e]);
            if (n < 1024) {
                float pre = sum + g_bias[3072 + n];
                g_rh[r * 1024 + n] = sigm(pre) * __ldcg(&g_cat[r * 2048 + 1024 + n]);
            } else if (n < 2048) {
                int j = n - 1024;
                g_z[r * 1024 + j] = sigm(sum + g_bias[4096 + j]);
            } else {
                g_xh1[r * 1024 + n - 2048] = sum;
            }
        }
        grid_bar(gen);
        // ---- Phase D: (r1*h1) @ Wh1_h  (N=1024: 4 x 32) ----
        if (cta < 128) {
            int nt = cta & 3, sp = cta >> 2;
            phase_gemm(g_rh, 1024, g_W1B, 1024, 1024, nt, sp, sp * 32, sp * 32 + 32);
        }
        grid_bar(gen);
        for (int e = gtid; e < 65536; e += nthr) {
            int r = e >> 10, n = e & 1023;
            float sum = 0.f;
#pragma unroll
            for (int sp = 0; sp < 32; sp++) sum += __ldcg(&g_part[sp * 65536 + e]);
            float pre = sum + __ldcg(&g_xh1[e]) + g_bias[5120 + n];
            float hh = tanhf(pre);
            float z = __ldcg(&g_z[e]);
            float h = __ldcg(&g_cat[r * 2048 + 1024 + n]);
            float hn = (1.f - z) * h + z * hh;
            g_cat[r * 2048 + 1024 + n] = hn;
            g_top[(size_t)(sb + r) * 1024 + n] = hn;
        }
        grid_bar(gen);
    }
}

// ---------------- logits GEMM ------------------------------------------
__global__ __launch_bounds__(256) void k_logits(const float* __restrict__ Wout,
                                                const float* __restrict__ bout,
                                                float* __restrict__ out) {
    u64 acc[4][8] = {};
    int n0 = blockIdx.x * 256, m0 = blockIdx.y * 64;
    mm_core<false, false>(g_top, 1024, nullptr, nullptr, m0, Wout, VOCAB, n0, VOCAB, 0, 1024, acc);
    int tx = threadIdx.x & 15, ty = threadIdx.x >> 4;
    bool full = (n0 + 256 <= VOCAB);
#pragma unroll
    for (int i = 0; i < 4; i++) {
        size_t row = m0 + ty * 4 + i;
        int cb = n0 + tx * 16;
        if (full) {
            float* dst = &out[row * VOCAB + cb];
#pragma unroll
            for (int q = 0; q < 4; q++) {
                float2 p0 = unpack2(acc[i][2 * q]);
                float2 p1 = unpack2(acc[i][2 * q + 1]);
                float4 bb = *(const float4*)&bout[cb + 4 * q];
                *(float4*)(dst + 4 * q) =
                    make_float4(p0.x + bb.x, p0.y + bb.y, p1.x + bb.z, p1.y + bb.w);
            }
        } else {
#pragma unroll
            for (int j = 0; j < 8; j++) {
                float2 p = unpack2(acc[i][j]);
                int c = cb + 2 * j;
                if (c < VOCAB)     out[row * VOCAB + c]     = p.x + bout[c];
                if (c + 1 < VOCAB) out[row * VOCAB + c + 1] = p.y + bout[c + 1];
            }
        }
    }
}

// ---------------- final hidden state -----------------------------------
__global__ void k_final(float* __restrict__ out) {
    int idx = blockIdx.x * blockDim.x + threadIdx.x;
    if (idx < 2 * 64 * 1024) {
        int l = idx >> 16;
        int rem = idx & 65535;
        int b = rem >> 10, j = rem & 1023;
        out[(size_t)16384 * VOCAB + idx] = g_cat[b * 2048 + l * 1024 + j];
    }
}

// ---------------- launch ------------------------------------------------
extern "C" void kernel_launch(void* const* d_in, const int* in_sizes, int n_in,
                              void* d_out, int out_size) {
    const int*   inputs = (const int*)d_in[0];
    const float* hidden = (const float*)d_in[1];
    const float* Emb    = (const float*)d_in[2];
    const float* Wr0 = (const float*)d_in[3];  const float* br0 = (const float*)d_in[4];
    const float* Wz0 = (const float*)d_in[5];  const float* bz0 = (const float*)d_in[6];
    const float* Wh0 = (const float*)d_in[7];  const float* bh0 = (const float*)d_in[8];
    const float* Wr1 = (const float*)d_in[9];  const float* br1 = (const float*)d_in[10];
    const float* Wz1 = (const float*)d_in[11]; const float* bz1 = (const float*)d_in[12];
    const float* Wh1 = (const float*)d_in[13]; const float* bh1 = (const float*)d_in[14];
    const float* Wout = (const float*)d_in[15];
    const float* bout = (const float*)d_in[16];
    float* out = (float*)d_out;

    k_prep<<<24576, 256>>>(hidden, Wr0, Wz0, Wh0, Wr1, Wz1, Wh1,
                           br0, bz0, bh0, br1, bz1, bh1);
    k_embed<<<dim3(12, 256), 256>>>(inputs, Emb);
    k_rec_persist<<<148, 256>>>();
    k_logits<<<dim3(40, 256), 256>>>(Wout, bout, out);
    k_final<<<512, 256>>>(out);
}

// round 5
// speedup vs baseline: 1.7787x; 1.7787x over previous
#include <cuda_runtime.h>
#include <math.h>

#define S_LEN 256
#define BATCH 64
#define VOCAB 10000
#define EDIM  512
#define HDIM  1024

typedef unsigned long long u64;

// ---------------- packed fp32x2 helpers (sm_103a FFMA2) ----------------
__device__ __forceinline__ u64 pack2(float lo, float hi) {
    u64 r; asm("mov.b64 %0,{%1,%2};" : "=l"(r) : "f"(lo), "f"(hi)); return r;
}
__device__ __forceinline__ float2 unpack2(u64 v) {
    float2 f; asm("mov.b64 {%0,%1},%2;" : "=f"(f.x), "=f"(f.y) : "l"(v)); return f;
}
__device__ __forceinline__ void ffma2(u64 &c, u64 a, u64 b) {
    asm("fma.rn.f32x2 %0,%1,%2,%0;" : "+l"(c) : "l"(a), "l"(b));
}

// ---------------- scratch (static device memory; no allocations) -------
__device__ float g_W0X[512 * 3072];
__device__ float g_W0A[1024 * 2048];
__device__ float g_W0B[1024 * 1024];
__device__ float g_W1A[2048 * 3072];
__device__ float g_W1B[1024 * 1024];
__device__ float g_bias[6 * 1024];
__device__ float g_xpre[(size_t)16384 * 3072];
__device__ float g_top[(size_t)16384 * 1024];
__device__ float g_cat[64 * 2048];
__device__ float g_rh[64 * 1024];
__device__ float g_z[64 * 1024];
__device__ float g_xh1[64 * 1024];
__device__ float g_part[2359296];          // split-K partials
__device__ int   g_cnt1[32] = {};
__device__ int   g_root = 0;
__device__ int   g_gen = 0;

// ---------------- two-level grid barrier (148 co-resident CTAs) --------
__device__ __forceinline__ void grid_bar(int &gen) {
    __threadfence();
    __syncthreads();
    if (threadIdx.x == 0) {
        int g = blockIdx.x >> 3;
        int ngrp = ((int)gridDim.x + 7) >> 3;
        int gsz = min(8, (int)gridDim.x - (g << 3));
        if (atomicAdd(&g_cnt1[g], 1) == gsz - 1) {
            atomicExch(&g_cnt1[g], 0);
            if (atomicAdd(&g_root, 1) == ngrp - 1) {
                atomicExch(&g_root, 0);
                __threadfence();
                atomicAdd(&g_gen, 1);
            }
        }
        volatile int* vg = &g_gen;
        while (*vg - gen <= 0) { }
        __threadfence();
    }
    gen++;
    __syncthreads();
}

// ---------------- weight repack + state init ---------------------------
__global__ void k_prep(const float* __restrict__ hidden,
                       const float* __restrict__ Wr0, const float* __restrict__ Wz0,
                       const float* __restrict__ Wh0,
                       const float* __restrict__ Wr1, const float* __restrict__ Wz1,
                       const float* __restrict__ Wh1,
                       const float* __restrict__ br0, const float* __restrict__ bz0,
                       const float* __restrict__ bh0,
                       const float* __restrict__ br1, const float* __restrict__ bz1,
                       const float* __restrict__ bh1) {
    int i = blockIdx.x * blockDim.x + threadIdx.x;
    if (i < 512 * 3072) {
        int k = i / 3072, n = i % 3072;
        float v = (n < 1024) ? Wr0[k * 1024 + n]
                : (n < 2048) ? Wz0[k * 1024 + n - 1024]
                             : Wh0[k * 1024 + n - 2048];
        g_W0X[i] = v;
    }
    if (i < 1024 * 2048) {
        int k = i / 2048, n = i % 2048;
        g_W0A[i] = (n < 1024) ? Wr0[(512 + k) * 1024 + n]
                              : Wz0[(512 + k) * 1024 + n - 1024];
    }
    if (i < 1024 * 1024) {
        int k = i >> 10, n = i & 1023;
        g_W0B[i] = Wh0[(512 + k) * 1024 + n];
        g_W1B[i] = Wh1[(1024 + k) * 1024 + n];
    }
    if (i < 2048 * 3072) {
        int k = i / 3072, n = i % 3072;
        float v;
        if (n < 1024)      v = Wr1[k * 1024 + n];
        else if (n < 2048) v = Wz1[k * 1024 + n - 1024];
        else               v = (k < 1024) ? Wh1[k * 1024 + (n - 2048)] : 0.f;
        g_W1A[i] = v;
    }
    if (i < 1024) {
        g_bias[i]        = br0[i]; g_bias[1024 + i] = bz0[i]; g_bias[2048 + i] = bh0[i];
        g_bias[3072 + i] = br1[i]; g_bias[4096 + i] = bz1[i]; g_bias[5120 + i] = bh1[i];
    }
    if (i < 64 * 2048) {
        int b = i >> 11, j = i & 2047;
        g_cat[i] = (j < 1024) ? hidden[b * 1024 + j]
                              : hidden[65536 + b * 1024 + (j - 1024)];
    }
}

// ---------------- shared tile (single instance per kernel) -------------
struct SmTile {
    float As[32][64];    // A rows permuted: row m -> (m&3)*16 + (m>>2)
    float Bs[32][128];
    int   tok[64];
};

// ---------------- 64x128 tile GEMM core (FFMA2, conflict-free) ---------
// 256 threads = 16(tx) x 16(ty); per-thread 4 rows x 8 cols
// cols: tx*4..tx*4+3 and tx*4+64..tx*4+67
template <bool CGA, bool GATHER>
__device__ __forceinline__ void mm_core(SmTile* sm,
    const float* __restrict__ A, int lda,
    const float* __restrict__ Emb, const int* __restrict__ tokens, int m0,
    const float* __restrict__ B, int ldb, int n0, int Nvalid,
    int kbeg, int kend, u64 acc[4][4]) {
    const int tid = threadIdx.x;
    if (GATHER) {
        if (tid < 64) sm->tok[tid] = tokens[m0 + tid];
        __syncthreads();
    }
    const int tx = tid & 15, ty = tid >> 4;
    const bool fullN = (n0 + 128 <= Nvalid);
    for (int k0 = kbeg; k0 < kend; k0 += 32) {
        // A fill: 64 rows x 32 k (512 float4 slots)
#pragma unroll
        for (int i = 0; i < 2; i++) {
            int slot = tid + i * 256;
            int mm = slot >> 3, kk = (slot & 7) * 4;
            int kg = k0 + kk;
            float4 v = make_float4(0.f, 0.f, 0.f, 0.f);
            if (kg < kend) {
                const float* p;
                if (GATHER) p = &Emb[(size_t)sm->tok[mm] * EDIM + kg];
                else        p = &A[(size_t)(m0 + mm) * lda + kg];
                v = CGA ? __ldcg((const float4*)p) : *(const float4*)p;
            }
            int pm = (mm & 3) * 16 + (mm >> 2);
            sm->As[kk][pm]     = v.x; sm->As[kk + 1][pm] = v.y;
            sm->As[kk + 2][pm] = v.z; sm->As[kk + 3][pm] = v.w;
        }
        // B fill: 32 k x 128 n (1024 float4 slots)
#pragma unroll
        for (int i = 0; i < 4; i++) {
            int slot = tid + i * 256;
            int kk = slot >> 5, nn = (slot & 31) * 4;
            int kg = k0 + kk, ng = n0 + nn;
            float4 v = make_float4(0.f, 0.f, 0.f, 0.f);
            if (kg < kend) {
                if (fullN) {
                    v = *(const float4*)&B[(size_t)kg * ldb + ng];
                } else {
                    if (ng     < Nvalid) v.x = B[(size_t)kg * ldb + ng];
                    if (ng + 1 < Nvalid) v.y = B[(size_t)kg * ldb + ng + 1];
                    if (ng + 2 < Nvalid) v.z = B[(size_t)kg * ldb + ng + 2];
                    if (ng + 3 < Nvalid) v.w = B[(size_t)kg * ldb + ng + 3];
                }
            }
            *(float4*)&sm->Bs[kk][nn] = v;
        }
        __syncthreads();
#pragma unroll 8
        for (int k = 0; k < 32; k++) {
            ulonglong2 b0 = *(const ulonglong2*)&sm->Bs[k][tx * 4];
            ulonglong2 b1 = *(const ulonglong2*)&sm->Bs[k][64 + tx * 4];
#pragma unroll
            for (int i = 0; i < 4; i++) {
                float a = sm->As[k][i * 16 + ty];
                u64 a2 = pack2(a, a);
                ffma2(acc[i][0], a2, b0.x);
                ffma2(acc[i][1], a2, b0.y);
                ffma2(acc[i][2], a2, b1.x);
                ffma2(acc[i][3], a2, b1.y);
            }
        }
        __syncthreads();
    }
}

// ---------------- layer0 x-side precompute (gathered GEMM) -------------
__global__ __launch_bounds__(256) void k_embed(const int* __restrict__ inputs,
                                               const float* __restrict__ Emb) {
    __shared__ SmTile sm;
    u64 acc[4][4] = {};
    int n0 = blockIdx.x * 128, m0 = blockIdx.y * 64;
    mm_core<false, true>(&sm, nullptr, 0, Emb, inputs, m0, g_W0X, 3072, n0, 3072, 0, 512, acc);
    int tx = threadIdx.x & 15, ty = threadIdx.x >> 4;
#pragma unroll
    for (int i = 0; i < 4; i++) {
        size_t row = m0 + ty * 4 + i;
        float2 p0 = unpack2(acc[i][0]), p1 = unpack2(acc[i][1]);
        float2 p2 = unpack2(acc[i][2]), p3 = unpack2(acc[i][3]);
        *(float4*)&g_xpre[row * 3072 + n0 + tx * 4]      = make_float4(p0.x, p0.y, p1.x, p1.y);
        *(float4*)&g_xpre[row * 3072 + n0 + 64 + tx * 4] = make_float4(p2.x, p2.y, p3.x, p3.y);
    }
}

// ---------------- split-K partial GEMM inside persistent kernel --------
__device__ __forceinline__ void phase_gemm(SmTile* sm, const float* A, int lda,
                                           const float* B, int ldb, int N,
                                           int ntile, int sp, int kbeg, int kend) {
    u64 acc[4][4] = {};
    int n0 = ntile * 128;
    mm_core<true, false>(sm, A, lda, nullptr, nullptr, 0, B, ldb, n0, N, kbeg, kend, acc);
    float* part = g_part + (size_t)sp * 64 * N;
    int tx = threadIdx.x & 15, ty = threadIdx.x >> 4;
#pragma unroll
    for (int i = 0; i < 4; i++) {
        int r = ty * 4 + i;
        float2 p0 = unpack2(acc[i][0]), p1 = unpack2(acc[i][1]);
        float2 p2 = unpack2(acc[i][2]), p3 = unpack2(acc[i][3]);
        *(float4*)&part[(size_t)r * N + n0 + tx * 4]      = make_float4(p0.x, p0.y, p1.x, p1.y);
        *(float4*)&part[(size_t)r * N + n0 + 64 + tx * 4] = make_float4(p2.x, p2.y, p3.x, p3.y);
    }
}

__device__ __forceinline__ float sigm(float x) { return 1.f / (1.f + expf(-x)); }

// ---------------- persistent recurrent kernel --------------------------
__global__ __launch_bounds__(256) void k_rec_persist() {
    __shared__ SmTile sm;
    const int cta = blockIdx.x, tid = threadIdx.x;
    const int gtid = cta * 256 + tid;
    const int nthr = (int)gridDim.x * 256;
    int gen = *(volatile int*)&g_gen;

    for (int s = 0; s < S_LEN; s++) {
        const int sb = s * BATCH;
        // ---- Phase A: h0 @ [Wr0_h|Wz0_h]  (N=2048: 16 nt x 8 sp, K128) ----
        if (cta < 128) {
            int nt = cta & 15, sp = cta >> 4;
            phase_gemm(&sm, g_cat, 2048, g_W0A, 2048, 2048, nt, sp, sp * 128, sp * 128 + 128);
        }
        grid_bar(gen);
        for (int e = gtid; e < 131072; e += nthr) {
            int r = e >> 11, n = e & 2047;
            float sum = 0.f;
#pragma unroll
            for (int sp = 0; sp < 8; sp++) sum += __ldcg(&g_part[sp * 131072 + e]);
            if (n < 1024) {
                float pre = sum + g_xpre[(size_t)(sb + r) * 3072 + n] + g_bias[n];
                g_rh[r * 1024 + n] = sigm(pre) * __ldcg(&g_cat[r * 2048 + n]);
            } else {
                int j = n - 1024;
                float pre = sum + g_xpre[(size_t)(sb + r) * 3072 + 1024 + j] + g_bias[1024 + j];
                g_z[r * 1024 + j] = sigm(pre);
            }
        }
        grid_bar(gen);
        // ---- Phase B: (r*h0) @ Wh0_h  (N=1024: 8 nt x 16 sp, K64) ----
        if (cta < 128) {
            int nt = cta & 7, sp = cta >> 3;
            phase_gemm(&sm, g_rh, 1024, g_W0B, 1024, 1024, nt, sp, sp * 64, sp * 64 + 64);
        }
        grid_bar(gen);
        for (int e = gtid; e < 65536; e += nthr) {
            int r = e >> 10, n = e & 1023;
            float sum = 0.f;
#pragma unroll
            for (int sp = 0; sp < 16; sp++) sum += __ldcg(&g_part[sp * 65536 + e]);
            float pre = sum + g_xpre[(size_t)(sb + r) * 3072 + 2048 + n] + g_bias[2048 + n];
            float hh = tanhf(pre);
            float z = __ldcg(&g_z[e]);
            float h = __ldcg(&g_cat[r * 2048 + n]);
            g_cat[r * 2048 + n] = (1.f - z) * h + z * hh;
        }
        grid_bar(gen);
        // ---- Phase C: [h0new|h1] @ [Wr1|Wz1|Wh1_x]  (N=3072: 24 nt x 6 sp, K352) ----
        if (cta < 144) {
            int nt = cta % 24, sp = cta / 24;
            int kb = sp * 352, ke = min(2048, kb + 352);
            phase_gemm(&sm, g_cat, 2048, g_W1A, 3072, 3072, nt, sp, kb, ke);
        }
        grid_bar(gen);
        for (int e = gtid; e < 196608; e += nthr) {
            int r = e / 3072, n = e - r * 3072;
            float sum = 0.f;
#pragma unroll
            for (int sp = 0; sp < 6; sp++) sum += __ldcg(&g_part[sp * 196608 + e]);
            if (n < 1024) {
                float pre = sum + g_bias[3072 + n];
                g_rh[r * 1024 + n] = sigm(pre) * __ldcg(&g_cat[r * 2048 + 1024 + n]);
            } else if (n < 2048) {
                int j = n - 1024;
                g_z[r * 1024 + j] = sigm(sum + g_bias[4096 + j]);
            } else {
                g_xh1[r * 1024 + n - 2048] = sum;
            }
        }
        grid_bar(gen);
        // ---- Phase D: (r1*h1) @ Wh1_h  (N=1024: 8 nt x 16 sp, K64) ----
        if (cta < 128) {
            int nt = cta & 7, sp = cta >> 3;
            phase_gemm(&sm, g_rh, 1024, g_W1B, 1024, 1024, nt, sp, sp * 64, sp * 64 + 64);
        }
        grid_bar(gen);
        for (int e = gtid; e < 65536; e += nthr) {
            int r = e >> 10, n = e & 1023;
            float sum = 0.f;
#pragma unroll
            for (int sp = 0; sp < 16; sp++) sum += __ldcg(&g_part[sp * 65536 + e]);
            float pre = sum + __ldcg(&g_xh1[e]) + g_bias[5120 + n];
            float hh = tanhf(pre);
            float z = __ldcg(&g_z[e]);
            float h = __ldcg(&g_cat[r * 2048 + 1024 + n]);
            float hn = (1.f - z) * h + z * hh;
            g_cat[r * 2048 + 1024 + n] = hn;
            g_top[(size_t)(sb + r) * 1024 + n] = hn;
        }
        grid_bar(gen);
    }
}

// ---------------- logits GEMM ------------------------------------------
__global__ __launch_bounds__(256) void k_logits(const float* __restrict__ Wout,
                                                const float* __restrict__ bout,
                                                float* __restrict__ out) {
    __shared__ SmTile sm;
    u64 acc[4][4] = {};
    int n0 = blockIdx.x * 128, m0 = blockIdx.y * 64;
    mm_core<false, false>(&sm, g_top, 1024, nullptr, nullptr, m0, Wout, VOCAB, n0, VOCAB, 0, 1024, acc);
    int tx = threadIdx.x & 15, ty = threadIdx.x >> 4;
    bool full = (n0 + 128 <= VOCAB);
#pragma unroll
    for (int i = 0; i < 4; i++) {
        size_t row = m0 + ty * 4 + i;
        float2 p[4] = { unpack2(acc[i][0]), unpack2(acc[i][1]),
                        unpack2(acc[i][2]), unpack2(acc[i][3]) };
        int c0 = n0 + tx * 4, c1 = n0 + 64 + tx * 4;
        if (full) {
            float4 b0 = *(const float4*)&bout[c0];
            float4 b1 = *(const float4*)&bout[c1];
            *(float4*)&out[row * VOCAB + c0] =
                make_float4(p[0].x + b0.x, p[0].y + b0.y, p[1].x + b0.z, p[1].y + b0.w);
            *(float4*)&out[row * VOCAB + c1] =
                make_float4(p[2].x + b1.x, p[2].y + b1.y, p[3].x + b1.z, p[3].y + b1.w);
        } else {
            float vals[8] = { p[0].x, p[0].y, p[1].x, p[1].y, p[2].x, p[2].y, p[3].x, p[3].y };
#pragma unroll
            for (int j = 0; j < 8; j++) {
                int c = (j < 4) ? (c0 + j) : (c1 + j - 4);
                if (c < VOCAB) out[row * VOCAB + c] = vals[j] + bout[c];
            }
        }
    }
}

// ---------------- final hidden state -----------------------------------
__global__ void k_final(float* __restrict__ out) {
    int idx = blockIdx.x * blockDim.x + threadIdx.x;
    if (idx < 2 * 64 * 1024) {
        int l = idx >> 16;
        int rem = idx & 65535;
        int b = rem >> 10, j = rem & 1023;
        out[(size_t)16384 * VOCAB + idx] = g_cat[b * 2048 + l * 1024 + j];
    }
}

// ---------------- launch ------------------------------------------------
extern "C" void kernel_launch(void* const* d_in, const int* in_sizes, int n_in,
                              void* d_out, int out_size) {
    const int*   inputs = (const int*)d_in[0];
    const float* hidden = (const float*)d_in[1];
    const float* Emb    = (const float*)d_in[2];
    const float* Wr0 = (const float*)d_in[3];  const float* br0 = (const float*)d_in[4];
    const float* Wz0 = (const float*)d_in[5];  const float* bz0 = (const float*)d_in[6];
    const float* Wh0 = (const float*)d_in[7];  const float* bh0 = (const float*)d_in[8];
    const float* Wr1 = (const float*)d_in[9];  const float* br1 = (const float*)d_in[10];
    const float* Wz1 = (const float*)d_in[11]; const float* bz1 = (const float*)d_in[12];
    const float* Wh1 = (const float*)d_in[13]; const float* bh1 = (const float*)d_in[14];
    const float* Wout = (const float*)d_in[15];
    const float* bout = (const float*)d_in[16];
    float* out = (float*)d_out;

    static bool attr_done = false;
    if (!attr_done) {
        cudaFuncSetAttribute(k_embed, cudaFuncAttributePreferredSharedMemoryCarveout, 100);
        cudaFuncSetAttribute(k_logits, cudaFuncAttributePreferredSharedMemoryCarveout, 100);
        cudaFuncSetAttribute(k_rec_persist, cudaFuncAttributePreferredSharedMemoryCarveout, 100);
        attr_done = true;
    }

    k_prep<<<24576, 256>>>(hidden, Wr0, Wz0, Wh0, Wr1, Wz1, Wh1,
                           br0, bz0, bh0, br1, bz1, bh1);
    k_embed<<<dim3(24, 256), 256>>>(inputs, Emb);
    k_rec_persist<<<148, 256>>>();
    k_logits<<<dim3(79, 256), 256>>>(Wout, bout, out);
    k_final<<<512, 256>>>(out);
}

// round 9
// speedup vs baseline: 2.2372x; 1.2578x over previous
#include <cuda_runtime.h>
#include <cuda_bf16.h>
#include <stdint.h>
#include <math.h>

#define S_LEN 256
#define BATCH 64
#define VOCAB 10000
#define EDIM  512
#define HDIM  1024

typedef unsigned long long u64;

// ---------------- packed fp32x2 helpers (sm_103a FFMA2) ----------------
__device__ __forceinline__ u64 pack2(float lo, float hi) {
    u64 r; asm("mov.b64 %0,{%1,%2};" : "=l"(r) : "f"(lo), "f"(hi)); return r;
}
__device__ __forceinline__ float2 unpack2(u64 v) {
    float2 f; asm("mov.b64 {%0,%1},%2;" : "=f"(f.x), "=f"(f.y) : "l"(v)); return f;
}
__device__ __forceinline__ void ffma2(u64 &c, u64 a, u64 b) {
    asm("fma.rn.f32x2 %0,%1,%2,%0;" : "+l"(c) : "l"(a), "l"(b));
}

// ---------------- warp-level mma helpers (sm_80+ PTX, works on sm_103) --
__device__ __forceinline__ uint32_t s2u(const void* p) {
    uint32_t a;
    asm("{ .reg .u64 t; cvta.to.shared.u64 t, %1; cvt.u32.u64 %0, t; }" : "=r"(a) : "l"(p));
    return a;
}
__device__ __forceinline__ void ldsm4(uint32_t* r, uint32_t addr) {
    asm volatile("ldmatrix.sync.aligned.m8n8.x4.shared.b16 {%0,%1,%2,%3}, [%4];"
        : "=r"(r[0]), "=r"(r[1]), "=r"(r[2]), "=r"(r[3]) : "r"(addr));
}
__device__ __forceinline__ void ldsm2(uint32_t* r, uint32_t addr) {
    asm volatile("ldmatrix.sync.aligned.m8n8.x2.shared.b16 {%0,%1}, [%2];"
        : "=r"(r[0]), "=r"(r[1]) : "r"(addr));
}
__device__ __forceinline__ void mma16816(float* d, const uint32_t* a, const uint32_t* b) {
    asm volatile(
        "mma.sync.aligned.m16n8k16.row.col.f32.bf16.bf16.f32 "
        "{%0,%1,%2,%3},{%4,%5,%6,%7},{%8,%9},{%0,%1,%2,%3};"
        : "+f"(d[0]), "+f"(d[1]), "+f"(d[2]), "+f"(d[3])
        : "r"(a[0]), "r"(a[1]), "r"(a[2]), "r"(a[3]), "r"(b[0]), "r"(b[1]));
}

// ---------------- scratch (static device memory; no allocations) -------
__device__ float g_W0X[512 * 3072];
__device__ float g_W0A[1024 * 2048];
__device__ float g_W0B[1024 * 1024];
__device__ float g_W1A[2048 * 3072];
__device__ float g_W1B[1024 * 1024];
__device__ float g_bias[6 * 1024];
__device__ float g_xpre[(size_t)16384 * 3072];
__device__ float g_top[(size_t)16384 * 1024];
__device__ float g_cat[64 * 2048];
__device__ float g_rh[64 * 1024];
__device__ float g_z[64 * 1024];
__device__ float g_xh1[64 * 1024];
__device__ float g_part[2359296];
__device__ int   g_cnt1[32] = {};
__device__ int   g_root = 0;
__device__ int   g_gen = 0;
// bf16 split operands for tensor-core logits
__device__ __nv_bfloat16 g_topH[(size_t)16384 * 1024];
__device__ __nv_bfloat16 g_topL[(size_t)16384 * 1024];
__device__ __nv_bfloat16 g_WoH[(size_t)10000 * 1024];
__device__ __nv_bfloat16 g_WoL[(size_t)10000 * 1024];

// ---------------- two-level grid barrier -------------------------------
__device__ __forceinline__ void grid_bar(int &gen) {
    __threadfence();
    __syncthreads();
    if (threadIdx.x == 0) {
        int g = blockIdx.x >> 3;
        int ngrp = ((int)gridDim.x + 7) >> 3;
        int gsz = min(8, (int)gridDim.x - (g << 3));
        if (atomicAdd(&g_cnt1[g], 1) == gsz - 1) {
            atomicExch(&g_cnt1[g], 0);
            if (atomicAdd(&g_root, 1) == ngrp - 1) {
                atomicExch(&g_root, 0);
                __threadfence();
                atomicAdd(&g_gen, 1);
            }
        }
        volatile int* vg = &g_gen;
        while (*vg - gen <= 0) { }
        __threadfence();
    }
    gen++;
    __syncthreads();
}

// ---------------- weight repack + state init ---------------------------
__global__ void k_prep(const float* __restrict__ hidden,
                       const float* __restrict__ Wr0, const float* __restrict__ Wz0,
                       const float* __restrict__ Wh0,
                       const float* __restrict__ Wr1, const float* __restrict__ Wz1,
                       const float* __restrict__ Wh1,
                       const float* __restrict__ br0, const float* __restrict__ bz0,
                       const float* __restrict__ bh0,
                       const float* __restrict__ br1, const float* __restrict__ bz1,
                       const float* __restrict__ bh1) {
    int i = blockIdx.x * blockDim.x + threadIdx.x;
    if (i < 512 * 3072) {
        int k = i / 3072, n = i % 3072;
        float v = (n < 1024) ? Wr0[k * 1024 + n]
                : (n < 2048) ? Wz0[k * 1024 + n - 1024]
                             : Wh0[k * 1024 + n - 2048];
        g_W0X[i] = v;
    }
    if (i < 1024 * 2048) {
        int k = i / 2048, n = i % 2048;
        g_W0A[i] = (n < 1024) ? Wr0[(512 + k) * 1024 + n]
                              : Wz0[(512 + k) * 1024 + n - 1024];
    }
    if (i < 1024 * 1024) {
        int k = i >> 10, n = i & 1023;
        g_W0B[i] = Wh0[(512 + k) * 1024 + n];
        g_W1B[i] = Wh1[(1024 + k) * 1024 + n];
    }
    if (i < 2048 * 3072) {
        int k = i / 3072, n = i % 3072;
        float v;
        if (n < 1024)      v = Wr1[k * 1024 + n];
        else if (n < 2048) v = Wz1[k * 1024 + n - 1024];
        else               v = (k < 1024) ? Wh1[k * 1024 + (n - 2048)] : 0.f;
        g_W1A[i] = v;
    }
    if (i < 1024) {
        g_bias[i]        = br0[i]; g_bias[1024 + i] = bz0[i]; g_bias[2048 + i] = bh0[i];
        g_bias[3072 + i] = br1[i]; g_bias[4096 + i] = bz1[i]; g_bias[5120 + i] = bh1[i];
    }
    if (i < 64 * 2048) {
        int b = i >> 11, j = i & 2047;
        g_cat[i] = (j < 1024) ? hidden[b * 1024 + j]
                              : hidden[65536 + b * 1024 + (j - 1024)];
    }
}

// ---------------- Wout split+transpose: [1024,10000] -> [n][k] hi/lo ---
__global__ __launch_bounds__(256) void k_wsplit(const float* __restrict__ Wout) {
    __shared__ float t[32][33];
    int tx = threadIdx.x & 31, ty = threadIdx.x >> 5;
    int n0 = blockIdx.x * 32, k0 = blockIdx.y * 32;
#pragma unroll
    for (int j = ty; j < 32; j += 8) {
        float v = 0.f;
        if (n0 + tx < VOCAB) v = Wout[(size_t)(k0 + j) * VOCAB + n0 + tx];
        t[j][tx] = v;
    }
    __syncthreads();
#pragma unroll
    for (int j = ty; j < 32; j += 8) {
        int n = n0 + j;
        if (n < VOCAB) {
            float v = t[tx][j];
            __nv_bfloat16 hi = __float2bfloat16(v);
            __nv_bfloat16 lo = __float2bfloat16(v - __bfloat162float(hi));
            g_WoH[(size_t)n * 1024 + k0 + tx] = hi;
            g_WoL[(size_t)n * 1024 + k0 + tx] = lo;
        }
    }
}

// ---------------- top split: f32 -> bf16 hi/lo -------------------------
__global__ __launch_bounds__(256) void k_tsplit() {
    size_t i = (size_t)blockIdx.x * 256 + threadIdx.x;
    if (i < (size_t)16384 * 1024) {
        float v = g_top[i];
        __nv_bfloat16 hi = __float2bfloat16(v);
        g_topH[i] = hi;
        g_topL[i] = __float2bfloat16(v - __bfloat162float(hi));
    }
}

// ---------------- shared tile (FFMA2 path) -----------------------------
struct SmTile {
    float As[32][64];
    float Bs[32][128];
    int   tok[64];
};

// ---------------- 64x128 tile GEMM core (FFMA2) ------------------------
template <bool CGA, bool GATHER>
__device__ __forceinline__ void mm_core(SmTile* sm,
    const float* __restrict__ A, int lda,
    const float* __restrict__ Emb, const int* __restrict__ tokens, int m0,
    const float* __restrict__ B, int ldb, int n0, int Nvalid,
    int kbeg, int kend, u64 acc[4][4]) {
    const int tid = threadIdx.x;
    if (GATHER) {
        if (tid < 64) sm->tok[tid] = tokens[m0 + tid];
        __syncthreads();
    }
    const int tx = tid & 15, ty = tid >> 4;
    const bool fullN = (n0 + 128 <= Nvalid);
    for (int k0 = kbeg; k0 < kend; k0 += 32) {
#pragma unroll
        for (int i = 0; i < 2; i++) {
            int slot = tid + i * 256;
            int mm = slot >> 3, kk = (slot & 7) * 4;
            int kg = k0 + kk;
            float4 v = make_float4(0.f, 0.f, 0.f, 0.f);
            if (kg < kend) {
                const float* p;
                if (GATHER) p = &Emb[(size_t)sm->tok[mm] * EDIM + kg];
                else        p = &A[(size_t)(m0 + mm) * lda + kg];
                v = CGA ? __ldcg((const float4*)p) : *(const float4*)p;
            }
            int pm = (mm & 3) * 16 + (mm >> 2);
            sm->As[kk][pm]     = v.x; sm->As[kk + 1][pm] = v.y;
            sm->As[kk + 2][pm] = v.z; sm->As[kk + 3][pm] = v.w;
        }
#pragma unroll
        for (int i = 0; i < 4; i++) {
            int slot = tid + i * 256;
            int kk = slot >> 5, nn = (slot & 31) * 4;
            int kg = k0 + kk, ng = n0 + nn;
            float4 v = make_float4(0.f, 0.f, 0.f, 0.f);
            if (kg < kend) {
                if (fullN) {
                    v = *(const float4*)&B[(size_t)kg * ldb + ng];
                } else {
                    if (ng     < Nvalid) v.x = B[(size_t)kg * ldb + ng];
                    if (ng + 1 < Nvalid) v.y = B[(size_t)kg * ldb + ng + 1];
                    if (ng + 2 < Nvalid) v.z = B[(size_t)kg * ldb + ng + 2];
                    if (ng + 3 < Nvalid) v.w = B[(size_t)kg * ldb + ng + 3];
                }
            }
            *(float4*)&sm->Bs[kk][nn] = v;
        }
        __syncthreads();
#pragma unroll 8
        for (int k = 0; k < 32; k++) {
            ulonglong2 b0 = *(const ulonglong2*)&sm->Bs[k][tx * 4];
            ulonglong2 b1 = *(const ulonglong2*)&sm->Bs[k][64 + tx * 4];
#pragma unroll
            for (int i = 0; i < 4; i++) {
                float a = sm->As[k][i * 16 + ty];
                u64 a2 = pack2(a, a);
                ffma2(acc[i][0], a2, b0.x);
                ffma2(acc[i][1], a2, b0.y);
                ffma2(acc[i][2], a2, b1.x);
                ffma2(acc[i][3], a2, b1.y);
            }
        }
        __syncthreads();
    }
}

// ---------------- layer0 x-side precompute -----------------------------
__global__ __launch_bounds__(256) void k_embed(const int* __restrict__ inputs,
                                               const float* __restrict__ Emb) {
    __shared__ SmTile sm;
    u64 acc[4][4] = {};
    int n0 = blockIdx.x * 128, m0 = blockIdx.y * 64;
    mm_core<false, true>(&sm, nullptr, 0, Emb, inputs, m0, g_W0X, 3072, n0, 3072, 0, 512, acc);
    int tx = threadIdx.x & 15, ty = threadIdx.x >> 4;
#pragma unroll
    for (int i = 0; i < 4; i++) {
        size_t row = m0 + ty * 4 + i;
        float2 p0 = unpack2(acc[i][0]), p1 = unpack2(acc[i][1]);
        float2 p2 = unpack2(acc[i][2]), p3 = unpack2(acc[i][3]);
        *(float4*)&g_xpre[row * 3072 + n0 + tx * 4]      = make_float4(p0.x, p0.y, p1.x, p1.y);
        *(float4*)&g_xpre[row * 3072 + n0 + 64 + tx * 4] = make_float4(p2.x, p2.y, p3.x, p3.y);
    }
}

// ---------------- split-K partial GEMM ---------------------------------
__device__ __forceinline__ void phase_gemm(SmTile* sm, const float* A, int lda,
                                           const float* B, int ldb, int N,
                                           int ntile, int sp, int kbeg, int kend) {
    u64 acc[4][4] = {};
    int n0 = ntile * 128;
    mm_core<true, false>(sm, A, lda, nullptr, nullptr, 0, B, ldb, n0, N, kbeg, kend, acc);
    float* part = g_part + (size_t)sp * 64 * N;
    int tx = threadIdx.x & 15, ty = threadIdx.x >> 4;
#pragma unroll
    for (int i = 0; i < 4; i++) {
        int r = ty * 4 + i;
        float2 p0 = unpack2(acc[i][0]), p1 = unpack2(acc[i][1]);
        float2 p2 = unpack2(acc[i][2]), p3 = unpack2(acc[i][3]);
        *(float4*)&part[(size_t)r * N + n0 + tx * 4]      = make_float4(p0.x, p0.y, p1.x, p1.y);
        *(float4*)&part[(size_t)r * N + n0 + 64 + tx * 4] = make_float4(p2.x, p2.y, p3.x, p3.y);
    }
}

__device__ __forceinline__ float sigm(float x) { return 1.f / (1.f + expf(-x)); }

// ---------------- persistent recurrent kernel --------------------------
__global__ __launch_bounds__(256) void k_rec_persist() {
    __shared__ SmTile sm;
    const int cta = blockIdx.x, tid = threadIdx.x;
    const int gtid = cta * 256 + tid;
    const int nthr = (int)gridDim.x * 256;
    int gen = *(volatile int*)&g_gen;

    for (int s = 0; s < S_LEN; s++) {
        const int sb = s * BATCH;
        if (cta < 128) {
            int nt = cta & 15, sp = cta >> 4;
            phase_gemm(&sm, g_cat, 2048, g_W0A, 2048, 2048, nt, sp, sp * 128, sp * 128 + 128);
        }
        grid_bar(gen);
        for (int e = gtid; e < 131072; e += nthr) {
            int r = e >> 11, n = e & 2047;
            float sum = 0.f;
#pragma unroll
            for (int sp = 0; sp < 8; sp++) sum += __ldcg(&g_part[sp * 131072 + e]);
            if (n < 1024) {
                float pre = sum + g_xpre[(size_t)(sb + r) * 3072 + n] + g_bias[n];
                g_rh[r * 1024 + n] = sigm(pre) * __ldcg(&g_cat[r * 2048 + n]);
            } else {
                int j = n - 1024;
                float pre = sum + g_xpre[(size_t)(sb + r) * 3072 + 1024 + j] + g_bias[1024 + j];
                g_z[r * 1024 + j] = sigm(pre);
            }
        }
        grid_bar(gen);
        if (cta < 128) {
            int nt = cta & 7, sp = cta >> 3;
            phase_gemm(&sm, g_rh, 1024, g_W0B, 1024, 1024, nt, sp, sp * 64, sp * 64 + 64);
        }
        grid_bar(gen);
        for (int e = gtid; e < 65536; e += nthr) {
            int r = e >> 10, n = e & 1023;
            float sum = 0.f;
#pragma unroll
            for (int sp = 0; sp < 16; sp++) sum += __ldcg(&g_part[sp * 65536 + e]);
            float pre = sum + g_xpre[(size_t)(sb + r) * 3072 + 2048 + n] + g_bias[2048 + n];
            float hh = tanhf(pre);
            float z = __ldcg(&g_z[e]);
            float h = __ldcg(&g_cat[r * 2048 + n]);
            g_cat[r * 2048 + n] = (1.f - z) * h + z * hh;
        }
        grid_bar(gen);
        if (cta < 144) {
            int nt = cta % 24, sp = cta / 24;
            int kb = sp * 352, ke = min(2048, kb + 352);
            phase_gemm(&sm, g_cat, 2048, g_W1A, 3072, 3072, nt, sp, kb, ke);
        }
        grid_bar(gen);
        for (int e = gtid; e < 196608; e += nthr) {
            int r = e / 3072, n = e - r * 3072;
            float sum = 0.f;
#pragma unroll
            for (int sp = 0; sp < 6; sp++) sum += __ldcg(&g_part[sp * 196608 + e]);
            if (n < 1024) {
                float pre = sum + g_bias[3072 + n];
                g_rh[r * 1024 + n] = sigm(pre) * __ldcg(&g_cat[r * 2048 + 1024 + n]);
            } else if (n < 2048) {
                int j = n - 1024;
                g_z[r * 1024 + j] = sigm(sum + g_bias[4096 + j]);
            } else {
                g_xh1[r * 1024 + n - 2048] = sum;
            }
        }
        grid_bar(gen);
        if (cta < 128) {
            int nt = cta & 7, sp = cta >> 3;
            phase_gemm(&sm, g_rh, 1024, g_W1B, 1024, 1024, nt, sp, sp * 64, sp * 64 + 64);
        }
        grid_bar(gen);
        for (int e = gtid; e < 65536; e += nthr) {
            int r = e >> 10, n = e & 1023;
            float sum = 0.f;
#pragma unroll
            for (int sp = 0; sp < 16; sp++) sum += __ldcg(&g_part[sp * 65536 + e]);
            float pre = sum + __ldcg(&g_xh1[e]) + g_bias[5120 + n];
            float hh = tanhf(pre);
            float z = __ldcg(&g_z[e]);
            float h = __ldcg(&g_cat[r * 2048 + 1024 + n]);
            float hn = (1.f - z) * h + z * hh;
            g_cat[r * 2048 + 1024 + n] = hn;
            g_top[(size_t)(sb + r) * 1024 + n] = hn;
        }
        grid_bar(gen);
    }
}

// ---------------- logits GEMM via mma.sync bf16 (split hi/lo, 3-pass) --
// CTA 128x128, BK=32, 8 warps (2m x 4n), warp tile 64x32.
// smem rows = 64B (32 bf16); 16B-group swizzle: g ^= (row>>1)&3.
__global__ __launch_bounds__(256) void k_logits_mma(const float* __restrict__ bout,
                                                    float* __restrict__ out) {
    __shared__ __align__(16) __nv_bfloat16 sAH[128 * 32];
    __shared__ __align__(16) __nv_bfloat16 sAL[128 * 32];
    __shared__ __align__(16) __nv_bfloat16 sBH[128 * 32];
    __shared__ __align__(16) __nv_bfloat16 sBL[128 * 32];
    const int tid = threadIdx.x, wid = tid >> 5, lane = tid & 31;
    const int m0 = blockIdx.y * 128, n0 = blockIdx.x * 128;
    const int wm = (wid & 1) * 64, wn = (wid >> 1) * 32;
    const uint32_t bAH = s2u(sAH), bAL = s2u(sAL), bBH = s2u(sBH), bBL = s2u(sBL);

    float acc[4][4][4];
#pragma unroll
    for (int i = 0; i < 4; i++)
#pragma unroll
        for (int j = 0; j < 4; j++)
#pragma unroll
            for (int q = 0; q < 4; q++) acc[i][j][q] = 0.f;

    for (int kc = 0; kc < 32; kc++) {
        const int k0 = kc * 32;
#pragma unroll
        for (int h = 0; h < 2; h++) {
            int row = (tid >> 2) + h * 64;
            int g = tid & 3;
            uint32_t off = row * 64 + ((g ^ ((row >> 1) & 3)) << 4);
            size_t goA = (size_t)(m0 + row) * 1024 + k0 + g * 8;
            *(uint4*)((char*)sAH + off) = *(const uint4*)&g_topH[goA];
            *(uint4*)((char*)sAL + off) = *(const uint4*)&g_topL[goA];
            uint4 vh = make_uint4(0, 0, 0, 0), vl = make_uint4(0, 0, 0, 0);
            if (n0 + row < VOCAB) {
                size_t goB = (size_t)(n0 + row) * 1024 + k0 + g * 8;
                vh = *(const uint4*)&g_WoH[goB];
                vl = *(const uint4*)&g_WoL[goB];
            }
            *(uint4*)((char*)sBH + off) = vh;
            *(uint4*)((char*)sBL + off) = vl;
        }
        __syncthreads();
#pragma unroll
        for (int kb = 0; kb < 32; kb += 16) {
            uint32_t aH[4][4], aL[4][4], bH[4][2], bL[4][2];
            int ar = wm + (lane & 15);
            int ag = (kb >> 3) + (lane >> 4);
#pragma unroll
            for (int mf = 0; mf < 4; mf++) {
                int m = ar + mf * 16;
                uint32_t off = m * 64 + ((ag ^ ((m >> 1) & 3)) << 4);
                ldsm4(aH[mf], bAH + off);
                ldsm4(aL[mf], bAL + off);
            }
            int br = wn + (lane & 7);
            int bg = (kb >> 3) + ((lane >> 3) & 1);
#pragma unroll
            for (int nf = 0; nf < 4; nf++) {
                int n = br + nf * 8;
                uint32_t off = n * 64 + ((bg ^ ((n >> 1) & 3)) << 4);
                ldsm2(bH[nf], bBH + off);
                ldsm2(bL[nf], bBL + off);
            }
#pragma unroll
            for (int mf = 0; mf < 4; mf++)
#pragma unroll
                for (int nf = 0; nf < 4; nf++) {
                    mma16816(acc[mf][nf], aH[mf], bH[nf]);
                    mma16816(acc[mf][nf], aH[mf], bL[nf]);
                    mma16816(acc[mf][nf], aL[mf], bH[nf]);
                }
        }
        __syncthreads();
    }

    // epilogue: frag layout -> gmem (+bias)
    int r0 = m0 + wm + (lane >> 2);
    int c0 = n0 + wn + (lane & 3) * 2;
#pragma unroll
    for (int mf = 0; mf < 4; mf++)
#pragma unroll
        for (int nf = 0; nf < 4; nf++) {
            int r = r0 + mf * 16, c = c0 + nf * 8;
            if (c < VOCAB) {
                float bx = bout[c], by = bout[c + 1];
                *(float2*)&out[(size_t)r * VOCAB + c] =
                    make_float2(acc[mf][nf][0] + bx, acc[mf][nf][1] + by);
                *(float2*)&out[(size_t)(r + 8) * VOCAB + c] =
                    make_float2(acc[mf][nf][2] + bx, acc[mf][nf][3] + by);
            }
        }
}

// ---------------- final hidden state -----------------------------------
__global__ void k_final(float* __restrict__ out) {
    int idx = blockIdx.x * blockDim.x + threadIdx.x;
    if (idx < 2 * 64 * 1024) {
        int l = idx >> 16;
        int rem = idx & 65535;
        int b = rem >> 10, j = rem & 1023;
        out[(size_t)16384 * VOCAB + idx] = g_cat[b * 2048 + l * 1024 + j];
    }
}

// ---------------- launch ------------------------------------------------
extern "C" void kernel_launch(void* const* d_in, const int* in_sizes, int n_in,
                              void* d_out, int out_size) {
    const int*   inputs = (const int*)d_in[0];
    const float* hidden = (const float*)d_in[1];
    const float* Emb    = (const float*)d_in[2];
    const float* Wr0 = (const float*)d_in[3];  const float* br0 = (const float*)d_in[4];
    const float* Wz0 = (const float*)d_in[5];  const float* bz0 = (const float*)d_in[6];
    const float* Wh0 = (const float*)d_in[7];  const float* bh0 = (const float*)d_in[8];
    const float* Wr1 = (const float*)d_in[9];  const float* br1 = (const float*)d_in[10];
    const float* Wz1 = (const float*)d_in[11]; const float* bz1 = (const float*)d_in[12];
    const float* Wh1 = (const float*)d_in[13]; const float* bh1 = (const float*)d_in[14];
    const float* Wout = (const float*)d_in[15];
    const float* bout = (const float*)d_in[16];
    float* out = (float*)d_out;

    static bool attr_done = false;
    if (!attr_done) {
        cudaFuncSetAttribute(k_embed, cudaFuncAttributePreferredSharedMemoryCarveout, 100);
        cudaFuncSetAttribute(k_rec_persist, cudaFuncAttributePreferredSharedMemoryCarveout, 100);
        attr_done = true;
    }

    k_prep<<<24576, 256>>>(hidden, Wr0, Wz0, Wh0, Wr1, Wz1, Wh1,
                           br0, bz0, bh0, br1, bz1, bh1);
    k_wsplit<<<dim3(313, 32), 256>>>(Wout);
    k_embed<<<dim3(24, 256), 256>>>(inputs, Emb);
    k_rec_persist<<<148, 256>>>();
    k_tsplit<<<65536, 256>>>();
    k_logits_mma<<<dim3(79, 128), 256>>>(bout, out);
    k_final<<<512, 256>>>(out);
}

// round 10
// speedup vs baseline: 3.1859x; 1.4241x over previous
#include <cuda_runtime.h>
#include <cuda_bf16.h>
#include <stdint.h>
#include <math.h>

#define S_LEN 256
#define BATCH 64
#define VOCAB 10000
#define EDIM  512
#define HDIM  1024

typedef unsigned long long u64;

// ---------------- packed fp32x2 helpers (sm_103a FFMA2) ----------------
__device__ __forceinline__ u64 pack2(float lo, float hi) {
    u64 r; asm("mov.b64 %0,{%1,%2};" : "=l"(r) : "f"(lo), "f"(hi)); return r;
}
__device__ __forceinline__ float2 unpack2(u64 v) {
    float2 f; asm("mov.b64 {%0,%1},%2;" : "=f"(f.x), "=f"(f.y) : "l"(v)); return f;
}
__device__ __forceinline__ void ffma2(u64 &c, u64 a, u64 b) {
    asm("fma.rn.f32x2 %0,%1,%2,%0;" : "+l"(c) : "l"(a), "l"(b));
}

// ---------------- warp-level mma helpers --------------------------------
__device__ __forceinline__ uint32_t s2u(const void* p) {
    uint32_t a;
    asm("{ .reg .u64 t; cvta.to.shared.u64 t, %1; cvt.u32.u64 %0, t; }" : "=r"(a) : "l"(p));
    return a;
}
__device__ __forceinline__ void ldsm4(uint32_t* r, uint32_t addr) {
    asm volatile("ldmatrix.sync.aligned.m8n8.x4.shared.b16 {%0,%1,%2,%3}, [%4];"
        : "=r"(r[0]), "=r"(r[1]), "=r"(r[2]), "=r"(r[3]) : "r"(addr));
}
__device__ __forceinline__ void ldsm2(uint32_t* r, uint32_t addr) {
    asm volatile("ldmatrix.sync.aligned.m8n8.x2.shared.b16 {%0,%1}, [%2];"
        : "=r"(r[0]), "=r"(r[1]) : "r"(addr));
}
__device__ __forceinline__ void mma16816(float* d, const uint32_t* a, const uint32_t* b) {
    asm volatile(
        "mma.sync.aligned.m16n8k16.row.col.f32.bf16.bf16.f32 "
        "{%0,%1,%2,%3},{%4,%5,%6,%7},{%8,%9},{%0,%1,%2,%3};"
        : "+f"(d[0]), "+f"(d[1]), "+f"(d[2]), "+f"(d[3])
        : "r"(a[0]), "r"(a[1]), "r"(a[2]), "r"(a[3]), "r"(b[0]), "r"(b[1]));
}

// ---------------- scratch (static device memory) ------------------------
__device__ float g_W0X[512 * 3072];
__device__ float g_bias[6 * 1024];
__device__ float g_xpre[(size_t)16384 * 3072];
__device__ float g_cat[64 * 2048];
__device__ float g_z[64 * 1024];
__device__ float g_xh1[64 * 1024];
__device__ float g_part[2359296];
__device__ int   g_cnt1[32] = {};
__device__ int   g_root = 0;
__device__ int   g_gen = 0;
// bf16 hi/lo recurrent weights, [n][k] layout
__device__ __nv_bfloat16 g_W0An_H[(size_t)2048 * 1024], g_W0An_L[(size_t)2048 * 1024];
__device__ __nv_bfloat16 g_W0Bn_H[(size_t)1024 * 1024], g_W0Bn_L[(size_t)1024 * 1024];
__device__ __nv_bfloat16 g_W1An_H[(size_t)3072 * 2048], g_W1An_L[(size_t)3072 * 2048];
__device__ __nv_bfloat16 g_W1Bn_H[(size_t)1024 * 1024], g_W1Bn_L[(size_t)1024 * 1024];
// bf16 hi/lo states
__device__ __nv_bfloat16 g_catH[64 * 2048], g_catL[64 * 2048];
__device__ __nv_bfloat16 g_rhH[64 * 1024], g_rhL[64 * 1024];
// bf16 split logits operands
__device__ __nv_bfloat16 g_topH[(size_t)16384 * 1024];
__device__ __nv_bfloat16 g_topL[(size_t)16384 * 1024];
__device__ __nv_bfloat16 g_WoH[(size_t)10000 * 1024];
__device__ __nv_bfloat16 g_WoL[(size_t)10000 * 1024];

// ---------------- two-level grid barrier -------------------------------
__device__ __forceinline__ void grid_bar(int &gen) {
    __threadfence();
    __syncthreads();
    if (threadIdx.x == 0) {
        int g = blockIdx.x >> 3;
        int ngrp = ((int)gridDim.x + 7) >> 3;
        int gsz = min(8, (int)gridDim.x - (g << 3));
        if (atomicAdd(&g_cnt1[g], 1) == gsz - 1) {
            atomicExch(&g_cnt1[g], 0);
            if (atomicAdd(&g_root, 1) == ngrp - 1) {
                atomicExch(&g_root, 0);
                __threadfence();
                atomicAdd(&g_gen, 1);
            }
        }
        volatile int* vg = &g_gen;
        while (*vg - gen <= 0) { }
        __threadfence();
    }
    gen++;
    __syncthreads();
}

// ---------------- prep: W0X, bias, initial state -----------------------
__global__ void k_prep(const float* __restrict__ hidden,
                       const float* __restrict__ Wr0, const float* __restrict__ Wz0,
                       const float* __restrict__ Wh0,
                       const float* __restrict__ br0, const float* __restrict__ bz0,
                       const float* __restrict__ bh0,
                       const float* __restrict__ br1, const float* __restrict__ bz1,
                       const float* __restrict__ bh1) {
    int i = blockIdx.x * blockDim.x + threadIdx.x;
    if (i < 512 * 3072) {
        int k = i / 3072, n = i % 3072;
        float v = (n < 1024) ? Wr0[k * 1024 + n]
                : (n < 2048) ? Wz0[k * 1024 + n - 1024]
                             : Wh0[k * 1024 + n - 2048];
        g_W0X[i] = v;
    }
    if (i < 1024) {
        g_bias[i]        = br0[i]; g_bias[1024 + i] = bz0[i]; g_bias[2048 + i] = bh0[i];
        g_bias[3072 + i] = br1[i]; g_bias[4096 + i] = bz1[i]; g_bias[5120 + i] = bh1[i];
    }
    if (i < 64 * 2048) {
        int b = i >> 11, j = i & 2047;
        float v = (j < 1024) ? hidden[b * 1024 + j]
                             : hidden[65536 + b * 1024 + (j - 1024)];
        g_cat[i] = v;
        __nv_bfloat16 hi = __float2bfloat16(v);
        g_catH[i] = hi;
        g_catL[i] = __float2bfloat16(v - __bfloat162float(hi));
    }
}

// ---------------- recurrent weight repack: [k][n] -> [n][k] bf16 hi/lo --
__global__ __launch_bounds__(256) void k_wprep(
    const float* __restrict__ Wr0, const float* __restrict__ Wz0, const float* __restrict__ Wh0,
    const float* __restrict__ Wr1, const float* __restrict__ Wz1, const float* __restrict__ Wh1) {
    __shared__ float t[32][33];
    const int which = blockIdx.z;
    const int Ns[4] = {2048, 1024, 3072, 1024};
    const int Ks[4] = {1024, 1024, 2048, 1024};
    const int N = Ns[which], K = Ks[which];
    int n0 = blockIdx.x * 32, k0 = blockIdx.y * 32;
    if (n0 >= N || k0 >= K) return;
    int tx = threadIdx.x & 31, ty = threadIdx.x >> 5;
#pragma unroll
    for (int j = ty; j < 32; j += 8) {
        int k = k0 + j, n = n0 + tx;
        float v;
        if (which == 0)      v = (n < 1024) ? Wr0[(512 + k) * 1024 + n] : Wz0[(512 + k) * 1024 + n - 1024];
        else if (which == 1) v = Wh0[(512 + k) * 1024 + n];
        else if (which == 2) v = (n < 1024) ? Wr1[k * 1024 + n]
                               : (n < 2048) ? Wz1[k * 1024 + n - 1024]
                               : ((k < 1024) ? Wh1[k * 1024 + (n - 2048)] : 0.f);
        else                 v = Wh1[(1024 + k) * 1024 + n];
        t[j][tx] = v;
    }
    __syncthreads();
    __nv_bfloat16 *dH, *dL;
    if (which == 0)      { dH = g_W0An_H; dL = g_W0An_L; }
    else if (which == 1) { dH = g_W0Bn_H; dL = g_W0Bn_L; }
    else if (which == 2) { dH = g_W1An_H; dL = g_W1An_L; }
    else                 { dH = g_W1Bn_H; dL = g_W1Bn_L; }
#pragma unroll
    for (int j = ty; j < 32; j += 8) {
        int n = n0 + j, k = k0 + tx;
        float v = t[tx][j];
        __nv_bfloat16 hi = __float2bfloat16(v);
        dH[(size_t)n * K + k] = hi;
        dL[(size_t)n * K + k] = __float2bfloat16(v - __bfloat162float(hi));
    }
}

// ---------------- Wout split+transpose ---------------------------------
__global__ __launch_bounds__(256) void k_wsplit(const float* __restrict__ Wout) {
    __shared__ float t[32][33];
    int tx = threadIdx.x & 31, ty = threadIdx.x >> 5;
    int n0 = blockIdx.x * 32, k0 = blockIdx.y * 32;
#pragma unroll
    for (int j = ty; j < 32; j += 8) {
        float v = 0.f;
        if (n0 + tx < VOCAB) v = Wout[(size_t)(k0 + j) * VOCAB + n0 + tx];
        t[j][tx] = v;
    }
    __syncthreads();
#pragma unroll
    for (int j = ty; j < 32; j += 8) {
        int n = n0 + j;
        if (n < VOCAB) {
            float v = t[tx][j];
            __nv_bfloat16 hi = __float2bfloat16(v);
            g_WoH[(size_t)n * 1024 + k0 + tx] = hi;
            g_WoL[(size_t)n * 1024 + k0 + tx] = __float2bfloat16(v - __bfloat162float(hi));
        }
    }
}

// ---------------- shared tile + FFMA2 core (embed only) ----------------
struct SmTile {
    float As[32][64];
    float Bs[32][128];
    int   tok[64];
};
template <bool GATHER>
__device__ __forceinline__ void mm_core(SmTile* sm,
    const float* __restrict__ Emb, const int* __restrict__ tokens, int m0,
    const float* __restrict__ B, int ldb, int n0, int Nvalid,
    int kbeg, int kend, u64 acc[4][4]) {
    const int tid = threadIdx.x;
    if (GATHER) {
        if (tid < 64) sm->tok[tid] = tokens[m0 + tid];
        __syncthreads();
    }
    const int tx = tid & 15, ty = tid >> 4;
    for (int k0 = kbeg; k0 < kend; k0 += 32) {
#pragma unroll
        for (int i = 0; i < 2; i++) {
            int slot = tid + i * 256;
            int mm = slot >> 3, kk = (slot & 7) * 4;
            int kg = k0 + kk;
            float4 v = make_float4(0.f, 0.f, 0.f, 0.f);
            if (kg < kend) v = *(const float4*)&Emb[(size_t)sm->tok[mm] * EDIM + kg];
            int pm = (mm & 3) * 16 + (mm >> 2);
            sm->As[kk][pm]     = v.x; sm->As[kk + 1][pm] = v.y;
            sm->As[kk + 2][pm] = v.z; sm->As[kk + 3][pm] = v.w;
        }
#pragma unroll
        for (int i = 0; i < 4; i++) {
            int slot = tid + i * 256;
            int kk = slot >> 5, nn = (slot & 31) * 4;
            int kg = k0 + kk, ng = n0 + nn;
            float4 v = make_float4(0.f, 0.f, 0.f, 0.f);
            if (kg < kend) v = *(const float4*)&B[(size_t)kg * ldb + ng];
            *(float4*)&sm->Bs[kk][nn] = v;
        }
        __syncthreads();
#pragma unroll 8
        for (int k = 0; k < 32; k++) {
            ulonglong2 b0 = *(const ulonglong2*)&sm->Bs[k][tx * 4];
            ulonglong2 b1 = *(const ulonglong2*)&sm->Bs[k][64 + tx * 4];
#pragma unroll
            for (int i = 0; i < 4; i++) {
                float a = sm->As[k][i * 16 + ty];
                u64 a2 = pack2(a, a);
                ffma2(acc[i][0], a2, b0.x);
                ffma2(acc[i][1], a2, b0.y);
                ffma2(acc[i][2], a2, b1.x);
                ffma2(acc[i][3], a2, b1.y);
            }
        }
        __syncthreads();
    }
}

__global__ __launch_bounds__(256) void k_embed(const int* __restrict__ inputs,
                                               const float* __restrict__ Emb) {
    __shared__ SmTile sm;
    u64 acc[4][4] = {};
    int n0 = blockIdx.x * 128, m0 = blockIdx.y * 64;
    mm_core<true>(&sm, Emb, inputs, m0, g_W0X, 3072, n0, 3072, 0, 512, acc);
    int tx = threadIdx.x & 15, ty = threadIdx.x >> 4;
#pragma unroll
    for (int i = 0; i < 4; i++) {
        size_t row = m0 + ty * 4 + i;
        float2 p0 = unpack2(acc[i][0]), p1 = unpack2(acc[i][1]);
        float2 p2 = unpack2(acc[i][2]), p3 = unpack2(acc[i][3]);
        *(float4*)&g_xpre[row * 3072 + n0 + tx * 4]      = make_float4(p0.x, p0.y, p1.x, p1.y);
        *(float4*)&g_xpre[row * 3072 + n0 + 64 + tx * 4] = make_float4(p2.x, p2.y, p3.x, p3.y);
    }
}

// ---------------- mma.sync split-K partial GEMM (recurrence) -----------
// CTA tile 64(M) x 128(N), BK=32; 8 warps = 2(m) x 4(n), warp tile 32x32.
__device__ __forceinline__ void phase_mma(
    const __nv_bfloat16* __restrict__ AH, const __nv_bfloat16* __restrict__ AL, int lda,
    const __nv_bfloat16* __restrict__ BH, const __nv_bfloat16* __restrict__ BL, int ldbk,
    int N, int ntile, int sp, int kbeg, int kend) {
    __shared__ __align__(16) __nv_bfloat16 sAH[64 * 32];
    __shared__ __align__(16) __nv_bfloat16 sAL[64 * 32];
    __shared__ __align__(16) __nv_bfloat16 sBH[128 * 32];
    __shared__ __align__(16) __nv_bfloat16 sBL[128 * 32];
    const int tid = threadIdx.x, wid = tid >> 5, lane = tid & 31;
    const int n0 = ntile * 128;
    const int wm = (wid & 1) * 32, wn = (wid >> 1) * 32;
    const uint32_t bAH = s2u(sAH), bAL = s2u(sAL), bBH = s2u(sBH), bBL = s2u(sBL);
    float acc[2][4][4];
#pragma unroll
    for (int i = 0; i < 2; i++)
#pragma unroll
        for (int j = 0; j < 4; j++)
#pragma unroll
            for (int q = 0; q < 4; q++) acc[i][j][q] = 0.f;

    const int arow = tid >> 2, ag4 = tid & 3;
    const uint32_t aoff = arow * 64 + ((ag4 ^ ((arow >> 1) & 3)) << 4);
    for (int k0 = kbeg; k0 < kend; k0 += 32) {
        *(uint4*)((char*)sAH + aoff) = __ldcg((const uint4*)(AH + (size_t)arow * lda + k0 + ag4 * 8));
        *(uint4*)((char*)sAL + aoff) = __ldcg((const uint4*)(AL + (size_t)arow * lda + k0 + ag4 * 8));
#pragma unroll
        for (int h = 0; h < 2; h++) {
            int row = arow + h * 64;
            uint32_t off = row * 64 + ((ag4 ^ ((row >> 1) & 3)) << 4);
            size_t go = (size_t)(n0 + row) * ldbk + k0 + ag4 * 8;
            *(uint4*)((char*)sBH + off) = *(const uint4*)(BH + go);
            *(uint4*)((char*)sBL + off) = *(const uint4*)(BL + go);
        }
        __syncthreads();
#pragma unroll
        for (int kb = 0; kb < 32; kb += 16) {
            uint32_t aH[2][4], aL[2][4], bH[4][2], bL[4][2];
            int ag = (kb >> 3) + (lane >> 4);
#pragma unroll
            for (int mf = 0; mf < 2; mf++) {
                int m = wm + (lane & 15) + mf * 16;
                uint32_t off = m * 64 + ((ag ^ ((m >> 1) & 3)) << 4);
                ldsm4(aH[mf], bAH + off);
                ldsm4(aL[mf], bAL + off);
            }
            int bg = (kb >> 3) + ((lane >> 3) & 1);
#pragma unroll
            for (int nf = 0; nf < 4; nf++) {
                int n = wn + (lane & 7) + nf * 8;
                uint32_t off = n * 64 + ((bg ^ ((n >> 1) & 3)) << 4);
                ldsm2(bH[nf], bBH + off);
                ldsm2(bL[nf], bBL + off);
            }
#pragma unroll
            for (int mf = 0; mf < 2; mf++)
#pragma unroll
                for (int nf = 0; nf < 4; nf++) {
                    mma16816(acc[mf][nf], aH[mf], bH[nf]);
                    mma16816(acc[mf][nf], aH[mf], bL[nf]);
                    mma16816(acc[mf][nf], aL[mf], bH[nf]);
                }
        }
        __syncthreads();
    }
    float* part = g_part + (size_t)sp * 64 * N;
    int r0 = wm + (lane >> 2), c0 = wn + (lane & 3) * 2;
#pragma unroll
    for (int mf = 0; mf < 2; mf++)
#pragma unroll
        for (int nf = 0; nf < 4; nf++) {
            int r = r0 + mf * 16, c = n0 + c0 + nf * 8;
            *(float2*)&part[(size_t)r * N + c]       = make_float2(acc[mf][nf][0], acc[mf][nf][1]);
            *(float2*)&part[(size_t)(r + 8) * N + c] = make_float2(acc[mf][nf][2], acc[mf][nf][3]);
        }
}

__device__ __forceinline__ float sigm(float x) { return 1.f / (1.f + expf(-x)); }
__device__ __forceinline__ void split_bf16(float v, __nv_bfloat16* H, __nv_bfloat16* L, int idx) {
    __nv_bfloat16 hi = __float2bfloat16(v);
    H[idx] = hi;
    L[idx] = __float2bfloat16(v - __bfloat162float(hi));
}

// ---------------- persistent recurrent kernel --------------------------
__global__ __launch_bounds__(256) void k_rec_persist() {
    const int cta = blockIdx.x, tid = threadIdx.x;
    const int gtid = cta * 256 + tid;
    const int nthr = (int)gridDim.x * 256;
    int gen = *(volatile int*)&g_gen;

    for (int s = 0; s < S_LEN; s++) {
        const int sb = s * BATCH;
        // ---- G1: h0 @ W0A  (N=2048: 16 nt x 8 sp, K128) ----
        if (cta < 128) {
            int nt = cta & 15, sp = cta >> 4;
            phase_mma(g_catH, g_catL, 2048, g_W0An_H, g_W0An_L, 1024,
                      2048, nt, sp, sp * 128, sp * 128 + 128);
        }
        grid_bar(gen);
        for (int e = gtid; e < 131072; e += nthr) {
            int r = e >> 11, n = e & 2047;
            float sum = 0.f;
#pragma unroll
            for (int sp = 0; sp < 8; sp++) sum += __ldcg(&g_part[sp * 131072 + e]);
            if (n < 1024) {
                float pre = sum + g_xpre[(size_t)(sb + r) * 3072 + n] + g_bias[n];
                float rh = sigm(pre) * __ldcg(&g_cat[r * 2048 + n]);
                split_bf16(rh, g_rhH, g_rhL, r * 1024 + n);
            } else {
                int j = n - 1024;
                float pre = sum + g_xpre[(size_t)(sb + r) * 3072 + 1024 + j] + g_bias[1024 + j];
                g_z[r * 1024 + j] = sigm(pre);
            }
        }
        grid_bar(gen);
        // ---- G2: rh0 @ W0B  (N=1024: 8 nt x 16 sp, K64) ----
        if (cta < 128) {
            int nt = cta & 7, sp = cta >> 3;
            phase_mma(g_rhH, g_rhL, 1024, g_W0Bn_H, g_W0Bn_L, 1024,
                      1024, nt, sp, sp * 64, sp * 64 + 64);
        }
        grid_bar(gen);
        for (int e = gtid; e < 65536; e += nthr) {
            int r = e >> 10, n = e & 1023;
            float sum = 0.f;
#pragma unroll
            for (int sp = 0; sp < 16; sp++) sum += __ldcg(&g_part[sp * 65536 + e]);
            float pre = sum + g_xpre[(size_t)(sb + r) * 3072 + 2048 + n] + g_bias[2048 + n];
            float hh = tanhf(pre);
            float z = __ldcg(&g_z[e]);
            float h = __ldcg(&g_cat[r * 2048 + n]);
            float hn = (1.f - z) * h + z * hh;
            g_cat[r * 2048 + n] = hn;
            split_bf16(hn, g_catH, g_catL, r * 2048 + n);
        }
        grid_bar(gen);
        // ---- G3: [h0new|h1] @ W1A  (N=3072: 24 nt x 6 sp, K352) ----
        if (cta < 144) {
            int nt = cta % 24, sp = cta / 24;
            int kb = sp * 352, ke = min(2048, kb + 352);
            phase_mma(g_catH, g_catL, 2048, g_W1An_H, g_W1An_L, 2048,
                      3072, nt, sp, kb, ke);
        }
        grid_bar(gen);
        for (int e = gtid; e < 196608; e += nthr) {
            int r = e / 3072, n = e - r * 3072;
            float sum = 0.f;
#pragma unroll
            for (int sp = 0; sp < 6; sp++) sum += __ldcg(&g_part[sp * 196608 + e]);
            if (n < 1024) {
                float pre = sum + g_bias[3072 + n];
                float rh = sigm(pre) * __ldcg(&g_cat[r * 2048 + 1024 + n]);
                split_bf16(rh, g_rhH, g_rhL, r * 1024 + n);
            } else if (n < 2048) {
                int j = n - 1024;
                g_z[r * 1024 + j] = sigm(sum + g_bias[4096 + j]);
            } else {
                g_xh1[r * 1024 + n - 2048] = sum;
            }
        }
        grid_bar(gen);
        // ---- G4: rh1 @ W1B  (N=1024: 8 nt x 16 sp, K64) ----
        if (cta < 128) {
            int nt = cta & 7, sp = cta >> 3;
            phase_mma(g_rhH, g_rhL, 1024, g_W1Bn_H, g_W1Bn_L, 1024,
                      1024, nt, sp, sp * 64, sp * 64 + 64);
        }
        grid_bar(gen);
        for (int e = gtid; e < 65536; e += nthr) {
            int r = e >> 10, n = e & 1023;
            float sum = 0.f;
#pragma unroll
            for (int sp = 0; sp < 16; sp++) sum += __ldcg(&g_part[sp * 65536 + e]);
            float pre = sum + __ldcg(&g_xh1[e]) + g_bias[5120 + n];
            float hh = tanhf(pre);
            float z = __ldcg(&g_z[e]);
            float h = __ldcg(&g_cat[r * 2048 + 1024 + n]);
            float hn = (1.f - z) * h + z * hh;
            g_cat[r * 2048 + 1024 + n] = hn;
            split_bf16(hn, g_catH, g_catL, r * 2048 + 1024 + n);
            __nv_bfloat16 hi = __float2bfloat16(hn);
            g_topH[(size_t)(sb + r) * 1024 + n] = hi;
            g_topL[(size_t)(sb + r) * 1024 + n] = __float2bfloat16(hn - __bfloat162float(hi));
        }
        grid_bar(gen);
    }
}

// ---------------- logits GEMM via mma.sync (hi/lo, 3-pass) -------------
__global__ __launch_bounds__(256) void k_logits_mma(const float* __restrict__ bout,
                                                    float* __restrict__ out) {
    __shared__ __align__(16) __nv_bfloat16 sAH[128 * 32];
    __shared__ __align__(16) __nv_bfloat16 sAL[128 * 32];
    __shared__ __align__(16) __nv_bfloat16 sBH[128 * 32];
    __shared__ __align__(16) __nv_bfloat16 sBL[128 * 32];
    const int tid = threadIdx.x, wid = tid >> 5, lane = tid & 31;
    const int m0 = blockIdx.y * 128, n0 = blockIdx.x * 128;
    const int wm = (wid & 1) * 64, wn = (wid >> 1) * 32;
    const uint32_t bAH = s2u(sAH), bAL = s2u(sAL), bBH = s2u(sBH), bBL = s2u(sBL);

    float acc[4][4][4];
#pragma unroll
    for (int i = 0; i < 4; i++)
#pragma unroll
        for (int j = 0; j < 4; j++)
#pragma unroll
            for (int q = 0; q < 4; q++) acc[i][j][q] = 0.f;

    for (int kc = 0; kc < 32; kc++) {
        const int k0 = kc * 32;
#pragma unroll
        for (int h = 0; h < 2; h++) {
            int row = (tid >> 2) + h * 64;
            int g = tid & 3;
            uint32_t off = row * 64 + ((g ^ ((row >> 1) & 3)) << 4);
            size_t goA = (size_t)(m0 + row) * 1024 + k0 + g * 8;
            *(uint4*)((char*)sAH + off) = *(const uint4*)&g_topH[goA];
            *(uint4*)((char*)sAL + off) = *(const uint4*)&g_topL[goA];
            uint4 vh = make_uint4(0, 0, 0, 0), vl = make_uint4(0, 0, 0, 0);
            if (n0 + row < VOCAB) {
                size_t goB = (size_t)(n0 + row) * 1024 + k0 + g * 8;
                vh = *(const uint4*)&g_WoH[goB];
                vl = *(const uint4*)&g_WoL[goB];
            }
            *(uint4*)((char*)sBH + off) = vh;
            *(uint4*)((char*)sBL + off) = vl;
        }
        __syncthreads();
#pragma unroll
        for (int kb = 0; kb < 32; kb += 16) {
            uint32_t aH[4][4], aL[4][4], bH[4][2], bL[4][2];
            int ar = wm + (lane & 15);
            int ag = (kb >> 3) + (lane >> 4);
#pragma unroll
            for (int mf = 0; mf < 4; mf++) {
                int m = ar + mf * 16;
                uint32_t off = m * 64 + ((ag ^ ((m >> 1) & 3)) << 4);
                ldsm4(aH[mf], bAH + off);
                ldsm4(aL[mf], bAL + off);
            }
            int br = wn + (lane & 7);
            int bg = (kb >> 3) + ((lane >> 3) & 1);
#pragma unroll
            for (int nf = 0; nf < 4; nf++) {
                int n = br + nf * 8;
                uint32_t off = n * 64 + ((bg ^ ((n >> 1) & 3)) << 4);
                ldsm2(bH[nf], bBH + off);
                ldsm2(bL[nf], bBL + off);
            }
#pragma unroll
            for (int mf = 0; mf < 4; mf++)
#pragma unroll
                for (int nf = 0; nf < 4; nf++) {
                    mma16816(acc[mf][nf], aH[mf], bH[nf]);
                    mma16816(acc[mf][nf], aH[mf], bL[nf]);
                    mma16816(acc[mf][nf], aL[mf], bH[nf]);
                }
        }
        __syncthreads();
    }

    int r0 = m0 + wm + (lane >> 2);
    int c0 = n0 + wn + (lane & 3) * 2;
#pragma unroll
    for (int mf = 0; mf < 4; mf++)
#pragma unroll
        for (int nf = 0; nf < 4; nf++) {
            int r = r0 + mf * 16, c = c0 + nf * 8;
            if (c < VOCAB) {
                float bx = bout[c], by = bout[c + 1];
                *(float2*)&out[(size_t)r * VOCAB + c] =
                    make_float2(acc[mf][nf][0] + bx, acc[mf][nf][1] + by);
                *(float2*)&out[(size_t)(r + 8) * VOCAB + c] =
                    make_float2(acc[mf][nf][2] + bx, acc[mf][nf][3] + by);
            }
        }
}

// ---------------- final hidden state -----------------------------------
__global__ void k_final(float* __restrict__ out) {
    int idx = blockIdx.x * blockDim.x + threadIdx.x;
    if (idx < 2 * 64 * 1024) {
        int l = idx >> 16;
        int rem = idx & 65535;
        int b = rem >> 10, j = rem & 1023;
        out[(size_t)16384 * VOCAB + idx] = g_cat[b * 2048 + l * 1024 + j];
    }
}

// ---------------- launch ------------------------------------------------
extern "C" void kernel_launch(void* const* d_in, const int* in_sizes, int n_in,
                              void* d_out, int out_size) {
    const int*   inputs = (const int*)d_in[0];
    const float* hidden = (const float*)d_in[1];
    const float* Emb    = (const float*)d_in[2];
    const float* Wr0 = (const float*)d_in[3];  const float* br0 = (const float*)d_in[4];
    const float* Wz0 = (const float*)d_in[5];  const float* bz0 = (const float*)d_in[6];
    const float* Wh0 = (const float*)d_in[7];  const float* bh0 = (const float*)d_in[8];
    const float* Wr1 = (const float*)d_in[9];  const float* br1 = (const float*)d_in[10];
    const float* Wz1 = (const float*)d_in[11]; const float* bz1 = (const float*)d_in[12];
    const float* Wh1 = (const float*)d_in[13]; const float* bh1 = (const float*)d_in[14];
    const float* Wout = (const float*)d_in[15];
    const float* bout = (const float*)d_in[16];
    float* out = (float*)d_out;

    static bool attr_done = false;
    if (!attr_done) {
        cudaFuncSetAttribute(k_embed, cudaFuncAttributePreferredSharedMemoryCarveout, 100);
        attr_done = true;
    }

    k_prep<<<6144, 256>>>(hidden, Wr0, Wz0, Wh0,
                          br0, bz0, bh0, br1, bz1, bh1);
    k_wprep<<<dim3(96, 64, 4), 256>>>(Wr0, Wz0, Wh0, Wr1, Wz1, Wh1);
    k_wsplit<<<dim3(313, 32), 256>>>(Wout);
    k_embed<<<dim3(24, 256), 256>>>(inputs, Emb);
    k_rec_persist<<<148, 256>>>();
    k_logits_mma<<<dim3(79, 128), 256>>>(bout, out);
    k_final<<<512, 256>>>(out);
}

// round 13
// speedup vs baseline: 3.5167x; 1.1038x over previous
#include <cuda_runtime.h>
#include <cuda_bf16.h>
#include <stdint.h>
#include <math.h>

#define S_LEN 256
#define BATCH 64
#define VOCAB 10000
#define EDIM  512
#define HDIM  1024

typedef unsigned long long u64;

// ---------------- warp-level mma helpers --------------------------------
__device__ __forceinline__ uint32_t s2u(const void* p) {
    uint32_t a;
    asm("{ .reg .u64 t; cvta.to.shared.u64 t, %1; cvt.u32.u64 %0, t; }" : "=r"(a) : "l"(p));
    return a;
}
__device__ __forceinline__ void ldsm4(uint32_t* r, uint32_t addr) {
    asm volatile("ldmatrix.sync.aligned.m8n8.x4.shared.b16 {%0,%1,%2,%3}, [%4];"
        : "=r"(r[0]), "=r"(r[1]), "=r"(r[2]), "=r"(r[3]) : "r"(addr));
}
__device__ __forceinline__ void ldsm2(uint32_t* r, uint32_t addr) {
    asm volatile("ldmatrix.sync.aligned.m8n8.x2.shared.b16 {%0,%1}, [%2];"
        : "=r"(r[0]), "=r"(r[1]) : "r"(addr));
}
__device__ __forceinline__ void mma16816(float* d, const uint32_t* a, const uint32_t* b) {
    asm volatile(
        "mma.sync.aligned.m16n8k16.row.col.f32.bf16.bf16.f32 "
        "{%0,%1,%2,%3},{%4,%5,%6,%7},{%8,%9},{%0,%1,%2,%3};"
        : "+f"(d[0]), "+f"(d[1]), "+f"(d[2]), "+f"(d[3])
        : "r"(a[0]), "r"(a[1]), "r"(a[2]), "r"(a[3]), "r"(b[0]), "r"(b[1]));
}

// ---------------- scratch (static device memory) ------------------------
__device__ float g_bias[6 * 1024];
__device__ float g_xpre[(size_t)16384 * 3072];
__device__ float g_cat[64 * 2048];
__device__ float g_z[64 * 1024];
__device__ float g_xh1[64 * 1024];
__device__ float g_part[2359296];
__device__ int   g_cnt1[32] = {};
__device__ int   g_root = 0;
__device__ int   g_gen = 0;
// bf16 hi/lo recurrent weights, [n][k] layout
__device__ __nv_bfloat16 g_W0An_H[(size_t)2048 * 1024], g_W0An_L[(size_t)2048 * 1024];
__device__ __nv_bfloat16 g_W0Bn_H[(size_t)1024 * 1024], g_W0Bn_L[(size_t)1024 * 1024];
__device__ __nv_bfloat16 g_W1An_H[(size_t)3072 * 2048], g_W1An_L[(size_t)3072 * 2048];
__device__ __nv_bfloat16 g_W1Bn_H[(size_t)1024 * 1024], g_W1Bn_L[(size_t)1024 * 1024];
// x-side weights [n][k] (n<3072, k<512) + embedding split
__device__ __nv_bfloat16 g_W0Xn_H[(size_t)3072 * 512], g_W0Xn_L[(size_t)3072 * 512];
__device__ __nv_bfloat16 g_EmbH[(size_t)10000 * 512], g_EmbL[(size_t)10000 * 512];
// bf16 hi/lo states
__device__ __nv_bfloat16 g_catH[64 * 2048], g_catL[64 * 2048];
__device__ __nv_bfloat16 g_rhH[64 * 1024], g_rhL[64 * 1024];
// bf16 split logits operands
__device__ __nv_bfloat16 g_topH[(size_t)16384 * 1024];
__device__ __nv_bfloat16 g_topL[(size_t)16384 * 1024];
__device__ __nv_bfloat16 g_WoH[(size_t)10000 * 1024];
__device__ __nv_bfloat16 g_WoL[(size_t)10000 * 1024];

// ---------------- two-level grid barrier (CG-style fences) -------------
__device__ __forceinline__ void grid_bar(int &gen) {
    __syncthreads();
    if (threadIdx.x == 0) {
        __threadfence();   // release for this CTA's prior writes
        int g = blockIdx.x >> 3;
        int ngrp = ((int)gridDim.x + 7) >> 3;
        int gsz = min(8, (int)gridDim.x - (g << 3));
        if (atomicAdd(&g_cnt1[g], 1) == gsz - 1) {
            atomicExch(&g_cnt1[g], 0);
            if (atomicAdd(&g_root, 1) == ngrp - 1) {
                atomicExch(&g_root, 0);
                __threadfence();
                atomicAdd(&g_gen, 1);
            }
        }
        volatile int* vg = &g_gen;
        while (*vg - gen <= 0) { }
        __threadfence();   // acquire
    }
    gen++;
    __syncthreads();
}

// ---------------- prep: bias + initial state ---------------------------
__global__ void k_prep(const float* __restrict__ hidden,
                       const float* __restrict__ br0, const float* __restrict__ bz0,
                       const float* __restrict__ bh0,
                       const float* __restrict__ br1, const float* __restrict__ bz1,
                       const float* __restrict__ bh1) {
    int i = blockIdx.x * blockDim.x + threadIdx.x;
    if (i < 1024) {
        g_bias[i]        = br0[i]; g_bias[1024 + i] = bz0[i]; g_bias[2048 + i] = bh0[i];
        g_bias[3072 + i] = br1[i]; g_bias[4096 + i] = bz1[i]; g_bias[5120 + i] = bh1[i];
    }
    if (i < 64 * 2048) {
        int b = i >> 11, j = i & 2047;
        float v = (j < 1024) ? hidden[b * 1024 + j]
                             : hidden[65536 + b * 1024 + (j - 1024)];
        g_cat[i] = v;
        __nv_bfloat16 hi = __float2bfloat16(v);
        g_catH[i] = hi;
        g_catL[i] = __float2bfloat16(v - __bfloat162float(hi));
    }
}

// ---------------- weight repack: [k][n] -> [n][k] bf16 hi/lo -----------
__global__ __launch_bounds__(256) void k_wprep(
    const float* __restrict__ Wr0, const float* __restrict__ Wz0, const float* __restrict__ Wh0,
    const float* __restrict__ Wr1, const float* __restrict__ Wz1, const float* __restrict__ Wh1) {
    __shared__ float t[32][33];
    const int which = blockIdx.z;
    const int Ns[5] = {2048, 1024, 3072, 1024, 3072};
    const int Ks[5] = {1024, 1024, 2048, 1024, 512};
    const int N = Ns[which], K = Ks[which];
    int n0 = blockIdx.x * 32, k0 = blockIdx.y * 32;
    if (n0 >= N || k0 >= K) return;
    int tx = threadIdx.x & 31, ty = threadIdx.x >> 5;
#pragma unroll
    for (int j = ty; j < 32; j += 8) {
        int k = k0 + j, n = n0 + tx;
        float v;
        if (which == 0)      v = (n < 1024) ? Wr0[(512 + k) * 1024 + n] : Wz0[(512 + k) * 1024 + n - 1024];
        else if (which == 1) v = Wh0[(512 + k) * 1024 + n];
        else if (which == 2) v = (n < 1024) ? Wr1[k * 1024 + n]
                               : (n < 2048) ? Wz1[k * 1024 + n - 1024]
                               : ((k < 1024) ? Wh1[k * 1024 + (n - 2048)] : 0.f);
        else if (which == 3) v = Wh1[(1024 + k) * 1024 + n];
        else                 v = (n < 1024) ? Wr0[k * 1024 + n]
                               : (n < 2048) ? Wz0[k * 1024 + n - 1024]
                               : Wh0[k * 1024 + n - 2048];
        t[j][tx] = v;
    }
    __syncthreads();
    __nv_bfloat16 *dH, *dL;
    if (which == 0)      { dH = g_W0An_H; dL = g_W0An_L; }
    else if (which == 1) { dH = g_W0Bn_H; dL = g_W0Bn_L; }
    else if (which == 2) { dH = g_W1An_H; dL = g_W1An_L; }
    else if (which == 3) { dH = g_W1Bn_H; dL = g_W1Bn_L; }
    else                 { dH = g_W0Xn_H; dL = g_W0Xn_L; }
#pragma unroll
    for (int j = ty; j < 32; j += 8) {
        int n = n0 + j, k = k0 + tx;
        float v = t[tx][j];
        __nv_bfloat16 hi = __float2bfloat16(v);
        dH[(size_t)n * K + k] = hi;
        dL[(size_t)n * K + k] = __float2bfloat16(v - __bfloat162float(hi));
    }
}

// ---------------- Emb split --------------------------------------------
__global__ __launch_bounds__(256) void k_esplit(const float* __restrict__ Emb) {
    size_t i = (size_t)blockIdx.x * 256 + threadIdx.x;
    if (i < (size_t)10000 * 512) {
        float v = Emb[i];
        __nv_bfloat16 hi = __float2bfloat16(v);
        g_EmbH[i] = hi;
        g_EmbL[i] = __float2bfloat16(v - __bfloat162float(hi));
    }
}

// ---------------- Wout split+transpose ---------------------------------
__global__ __launch_bounds__(256) void k_wsplit(const float* __restrict__ Wout) {
    __shared__ float t[32][33];
    int tx = threadIdx.x & 31, ty = threadIdx.x >> 5;
    int n0 = blockIdx.x * 32, k0 = blockIdx.y * 32;
#pragma unroll
    for (int j = ty; j < 32; j += 8) {
        float v = 0.f;
        if (n0 + tx < VOCAB) v = Wout[(size_t)(k0 + j) * VOCAB + n0 + tx];
        t[j][tx] = v;
    }
    __syncthreads();
#pragma unroll
    for (int j = ty; j < 32; j += 8) {
        int n = n0 + j;
        if (n < VOCAB) {
            float v = t[tx][j];
            __nv_bfloat16 hi = __float2bfloat16(v);
            g_WoH[(size_t)n * 1024 + k0 + tx] = hi;
            g_WoL[(size_t)n * 1024 + k0 + tx] = __float2bfloat16(v - __bfloat162float(hi));
        }
    }
}

// ---------------- embed GEMM via mma.sync (gathered A, hi/lo 3-pass) ---
// CTA 128x128, BK=32; output g_xpre = Emb[tok] @ W0X  (K=512)
__global__ __launch_bounds__(256) void k_embed_mma(const int* __restrict__ inputs) {
    __shared__ __align__(16) __nv_bfloat16 sAH[128 * 32];
    __shared__ __align__(16) __nv_bfloat16 sAL[128 * 32];
    __shared__ __align__(16) __nv_bfloat16 sBH[128 * 32];
    __shared__ __align__(16) __nv_bfloat16 sBL[128 * 32];
    __shared__ int stok[128];
    const int tid = threadIdx.x, wid = tid >> 5, lane = tid & 31;
    const int m0 = blockIdx.y * 128, n0 = blockIdx.x * 128;
    const int wm = (wid & 1) * 64, wn = (wid >> 1) * 32;
    const uint32_t bAH = s2u(sAH), bAL = s2u(sAL), bBH = s2u(sBH), bBL = s2u(sBL);
    if (tid < 128) stok[tid] = inputs[m0 + tid];
    __syncthreads();

    float acc[4][4][4];
#pragma unroll
    for (int i = 0; i < 4; i++)
#pragma unroll
        for (int j = 0; j < 4; j++)
#pragma unroll
            for (int q = 0; q < 4; q++) acc[i][j][q] = 0.f;

    for (int kc = 0; kc < 16; kc++) {
        const int k0 = kc * 32;
#pragma unroll
        for (int h = 0; h < 2; h++) {
            int row = (tid >> 2) + h * 64;
            int g = tid & 3;
            uint32_t off = row * 64 + ((g ^ ((row >> 1) & 3)) << 4);
            size_t goA = (size_t)stok[row] * 512 + k0 + g * 8;
            *(uint4*)((char*)sAH + off) = *(const uint4*)&g_EmbH[goA];
            *(uint4*)((char*)sAL + off) = *(const uint4*)&g_EmbL[goA];
            size_t goB = (size_t)(n0 + row) * 512 + k0 + g * 8;
            *(uint4*)((char*)sBH + off) = *(const uint4*)&g_W0Xn_H[goB];
            *(uint4*)((char*)sBL + off) = *(const uint4*)&g_W0Xn_L[goB];
        }
        __syncthreads();
#pragma unroll
        for (int kb = 0; kb < 32; kb += 16) {
            uint32_t aH[4][4], aL[4][4], bH[4][2], bL[4][2];
            int ar = wm + (lane & 15);
            int ag = (kb >> 3) + (lane >> 4);
#pragma unroll
            for (int mf = 0; mf < 4; mf++) {
                int m = ar + mf * 16;
                uint32_t off = m * 64 + ((ag ^ ((m >> 1) & 3)) << 4);
                ldsm4(aH[mf], bAH + off);
                ldsm4(aL[mf], bAL + off);
            }
            int br = wn + (lane & 7);
            int bg = (kb >> 3) + ((lane >> 3) & 1);
#pragma unroll
            for (int nf = 0; nf < 4; nf++) {
                int n = br + nf * 8;
                uint32_t off = n * 64 + ((bg ^ ((n >> 1) & 3)) << 4);
                ldsm2(bH[nf], bBH + off);
                ldsm2(bL[nf], bBL + off);
            }
#pragma unroll
            for (int mf = 0; mf < 4; mf++)
#pragma unroll
                for (int nf = 0; nf < 4; nf++) {
                    mma16816(acc[mf][nf], aH[mf], bH[nf]);
                    mma16816(acc[mf][nf], aH[mf], bL[nf]);
                    mma16816(acc[mf][nf], aL[mf], bH[nf]);
                }
        }
        __syncthreads();
    }
    int r0 = m0 + wm + (lane >> 2);
    int c0 = n0 + wn + (lane & 3) * 2;
#pragma unroll
    for (int mf = 0; mf < 4; mf++)
#pragma unroll
        for (int nf = 0; nf < 4; nf++) {
            int r = r0 + mf * 16, c = c0 + nf * 8;
            *(float2*)&g_xpre[(size_t)r * 3072 + c] = make_float2(acc[mf][nf][0], acc[mf][nf][1]);
            *(float2*)&g_xpre[(size_t)(r + 8) * 3072 + c] = make_float2(acc[mf][nf][2], acc[mf][nf][3]);
        }
}

// ---------------- mma.sync split-K partial GEMM (recurrence) -----------
// CTA 64(M) x 128(N), BK=32; 8 warps = 2(m) x 4(n), warp tile 32x32.
__device__ __forceinline__ void phase_mma(
    const __nv_bfloat16* __restrict__ AH, const __nv_bfloat16* __restrict__ AL, int lda,
    const __nv_bfloat16* __restrict__ BH, const __nv_bfloat16* __restrict__ BL, int ldbk,
    int N, int ntile, int sp, int kbeg, int kend) {
    __shared__ __align__(16) __nv_bfloat16 sAH[64 * 32];
    __shared__ __align__(16) __nv_bfloat16 sAL[64 * 32];
    __shared__ __align__(16) __nv_bfloat16 sBH[128 * 32];
    __shared__ __align__(16) __nv_bfloat16 sBL[128 * 32];
    const int tid = threadIdx.x, wid = tid >> 5, lane = tid & 31;
    const int n0 = ntile * 128;
    const int wm = (wid & 1) * 32, wn = (wid >> 1) * 32;
    const uint32_t bAH = s2u(sAH), bAL = s2u(sAL), bBH = s2u(sBH), bBL = s2u(sBL);
    float acc[2][4][4];
#pragma unroll
    for (int i = 0; i < 2; i++)
#pragma unroll
        for (int j = 0; j < 4; j++)
#pragma unroll
            for (int q = 0; q < 4; q++) acc[i][j][q] = 0.f;

    const int arow = tid >> 2, ag4 = tid & 3;
    const uint32_t aoff = arow * 64 + ((ag4 ^ ((arow >> 1) & 3)) << 4);
    for (int k0 = kbeg; k0 < kend; k0 += 32) {
        *(uint4*)((char*)sAH + aoff) = __ldcg((const uint4*)(AH + (size_t)arow * lda + k0 + ag4 * 8));
        *(uint4*)((char*)sAL + aoff) = __ldcg((const uint4*)(AL + (size_t)arow * lda + k0 + ag4 * 8));
#pragma unroll
        for (int h = 0; h < 2; h++) {
            int row = arow + h * 64;
            uint32_t off = row * 64 + ((ag4 ^ ((row >> 1) & 3)) << 4);
            size_t go = (size_t)(n0 + row) * ldbk + k0 + ag4 * 8;
            *(uint4*)((char*)sBH + off) = *(const uint4*)(BH + go);
            *(uint4*)((char*)sBL + off) = *(const uint4*)(BL + go);
        }
        __syncthreads();
#pragma unroll
        for (int kb = 0; kb < 32; kb += 16) {
            uint32_t aH[2][4], aL[2][4], bH[4][2], bL[4][2];
            int ag = (kb >> 3) + (lane >> 4);
#pragma unroll
            for (int mf = 0; mf < 2; mf++) {
                int m = wm + (lane & 15) + mf * 16;
                uint32_t off = m * 64 + ((ag ^ ((m >> 1) & 3)) << 4);
                ldsm4(aH[mf], bAH + off);
                ldsm4(aL[mf], bAL + off);
            }
            int bg = (kb >> 3) + ((lane >> 3) & 1);
#pragma unroll
            for (int nf = 0; nf < 4; nf++) {
                int n = wn + (lane & 7) + nf * 8;
                uint32_t off = n * 64 + ((bg ^ ((n >> 1) & 3)) << 4);
                ldsm2(bH[nf], bBH + off);
                ldsm2(bL[nf], bBL + off);
            }
#pragma unroll
            for (int mf = 0; mf < 2; mf++)
#pragma unroll
                for (int nf = 0; nf < 4; nf++) {
                    mma16816(acc[mf][nf], aH[mf], bH[nf]);
                    mma16816(acc[mf][nf], aH[mf], bL[nf]);
                    mma16816(acc[mf][nf], aL[mf], bH[nf]);
                }
        }
        __syncthreads();
    }
    float* part = g_part + (size_t)sp * 64 * N;
    int r0 = wm + (lane >> 2), c0 = wn + (lane & 3) * 2;
#pragma unroll
    for (int mf = 0; mf < 2; mf++)
#pragma unroll
        for (int nf = 0; nf < 4; nf++) {
            int r = r0 + mf * 16, c = n0 + c0 + nf * 8;
            *(float2*)&part[(size_t)r * N + c]       = make_float2(acc[mf][nf][0], acc[mf][nf][1]);
            *(float2*)&part[(size_t)(r + 8) * N + c] = make_float2(acc[mf][nf][2], acc[mf][nf][3]);
        }
}

__device__ __forceinline__ float sigm(float x) { return 1.f / (1.f + expf(-x)); }
__device__ __forceinline__ void split4(const float* v, __nv_bfloat16* H, __nv_bfloat16* L, int idx) {
    __nv_bfloat162 h0, h1, l0, l1;
    __nv_bfloat16 a = __float2bfloat16(v[0]), b = __float2bfloat16(v[1]);
    __nv_bfloat16 c = __float2bfloat16(v[2]), d = __float2bfloat16(v[3]);
    h0.x = a; h0.y = b; h1.x = c; h1.y = d;
    l0.x = __float2bfloat16(v[0] - __bfloat162float(a));
    l0.y = __float2bfloat16(v[1] - __bfloat162float(b));
    l1.x = __float2bfloat16(v[2] - __bfloat162float(c));
    l1.y = __float2bfloat16(v[3] - __bfloat162float(d));
    *(__nv_bfloat162*)&H[idx] = h0; *(__nv_bfloat162*)&H[idx + 2] = h1;
    *(__nv_bfloat162*)&L[idx] = l0; *(__nv_bfloat162*)&L[idx + 2] = l1;
}

// ---------------- persistent recurrent kernel --------------------------
__global__ __launch_bounds__(256) void k_rec_persist() {
    const int cta = blockIdx.x, tid = threadIdx.x;
    const int gtid = cta * 256 + tid;
    const int nthr = (int)gridDim.x * 256;
    int gen = *(volatile int*)&g_gen;

    for (int s = 0; s < S_LEN; s++) {
        const int sb = s * BATCH;
        // ---- G1: h0 @ W0A  (N=2048: 16 nt x 8 sp, K128) ----
        if (cta < 128) {
            int nt = cta & 15, sp = cta >> 4;
            phase_mma(g_catH, g_catL, 2048, g_W0An_H, g_W0An_L, 1024,
                      2048, nt, sp, sp * 128, sp * 128 + 128);
        }
        grid_bar(gen);
        for (int g4 = gtid; g4 < 32768; g4 += nthr) {
            int e = g4 * 4;
            int r = e >> 11, n = e & 2047;
            float4 s4 = make_float4(0.f, 0.f, 0.f, 0.f);
#pragma unroll
            for (int sp = 0; sp < 8; sp++) {
                float4 p = __ldcg((const float4*)&g_part[sp * 131072 + e]);
                s4.x += p.x; s4.y += p.y; s4.z += p.z; s4.w += p.w;
            }
            float4 xp = *(const float4*)&g_xpre[(size_t)(sb + r) * 3072 + n];
            float4 bi = *(const float4*)&g_bias[n];
            float pre[4] = { s4.x + xp.x + bi.x, s4.y + xp.y + bi.y,
                             s4.z + xp.z + bi.z, s4.w + xp.w + bi.w };
            if (n < 1024) {
                float4 cc = __ldcg((const float4*)&g_cat[r * 2048 + n]);
                float rh[4] = { sigm(pre[0]) * cc.x, sigm(pre[1]) * cc.y,
                                sigm(pre[2]) * cc.z, sigm(pre[3]) * cc.w };
                split4(rh, g_rhH, g_rhL, r * 1024 + n);
            } else {
                int j = n - 1024;
                *(float4*)&g_z[r * 1024 + j] =
                    make_float4(sigm(pre[0]), sigm(pre[1]), sigm(pre[2]), sigm(pre[3]));
            }
        }
        grid_bar(gen);
        // ---- G2: rh0 @ W0B  (N=1024: 8 nt x 8 sp, K128) ----
        if (cta < 64) {
            int nt = cta & 7, sp = cta >> 3;
            phase_mma(g_rhH, g_rhL, 1024, g_W0Bn_H, g_W0Bn_L, 1024,
                      1024, nt, sp, sp * 128, sp * 128 + 128);
        }
        grid_bar(gen);
        for (int g4 = gtid; g4 < 16384; g4 += nthr) {
            int e = g4 * 4;
            int r = e >> 10, n = e & 1023;
            float4 s4 = make_float4(0.f, 0.f, 0.f, 0.f);
#pragma unroll
            for (int sp = 0; sp < 8; sp++) {
                float4 p = __ldcg((const float4*)&g_part[sp * 65536 + e]);
                s4.x += p.x; s4.y += p.y; s4.z += p.z; s4.w += p.w;
            }
            float4 xp = *(const float4*)&g_xpre[(size_t)(sb + r) * 3072 + 2048 + n];
            float4 bi = *(const float4*)&g_bias[2048 + n];
            float4 z4 = __ldcg((const float4*)&g_z[e]);
            float4 h4 = __ldcg((const float4*)&g_cat[r * 2048 + n]);
            float hn[4];
            hn[0] = (1.f - z4.x) * h4.x + z4.x * tanhf(s4.x + xp.x + bi.x);
            hn[1] = (1.f - z4.y) * h4.y + z4.y * tanhf(s4.y + xp.y + bi.y);
            hn[2] = (1.f - z4.z) * h4.z + z4.z * tanhf(s4.z + xp.z + bi.z);
            hn[3] = (1.f - z4.w) * h4.w + z4.w * tanhf(s4.w + xp.w + bi.w);
            *(float4*)&g_cat[r * 2048 + n] = make_float4(hn[0], hn[1], hn[2], hn[3]);
            split4(hn, g_catH, g_catL, r * 2048 + n);
        }
        grid_bar(gen);
        // ---- G3: [h0new|h1] @ W1A  (N=3072: 24 nt x 6 sp, K352) ----
        if (cta < 144) {
            int nt = cta % 24, sp = cta / 24;
            int kb = sp * 352, ke = min(2048, kb + 352);
            phase_mma(g_catH, g_catL, 2048, g_W1An_H, g_W1An_L, 2048,
                      3072, nt, sp, kb, ke);
        }
        grid_bar(gen);
        for (int g4 = gtid; g4 < 49152; g4 += nthr) {
            int e = g4 * 4;
            int r = e / 3072, n = e - r * 3072;
            float4 s4 = make_float4(0.f, 0.f, 0.f, 0.f);
#pragma unroll
            for (int sp = 0; sp < 6; sp++) {
                float4 p = __ldcg((const float4*)&g_part[sp * 196608 + e]);
                s4.x += p.x; s4.y += p.y; s4.z += p.z; s4.w += p.w;
            }
            if (n < 1024) {
                float4 bi = *(const float4*)&g_bias[3072 + n];
                float4 cc = __ldcg((const float4*)&g_cat[r * 2048 + 1024 + n]);
                float rh[4] = { sigm(s4.x + bi.x) * cc.x, sigm(s4.y + bi.y) * cc.y,
                                sigm(s4.z + bi.z) * cc.z, sigm(s4.w + bi.w) * cc.w };
                split4(rh, g_rhH, g_rhL, r * 1024 + n);
            } else if (n < 2048) {
                int j = n - 1024;
                float4 bi = *(const float4*)&g_bias[4096 + j];
                *(float4*)&g_z[r * 1024 + j] = make_float4(
                    sigm(s4.x + bi.x), sigm(s4.y + bi.y), sigm(s4.z + bi.z), sigm(s4.w + bi.w));
            } else {
                *(float4*)&g_xh1[r * 1024 + n - 2048] = s4;
            }
        }
        grid_bar(gen);
        // ---- G4: rh1 @ W1B  (N=1024: 8 nt x 8 sp, K128) ----
        if (cta < 64) {
            int nt = cta & 7, sp = cta >> 3;
            phase_mma(g_rhH, g_rhL, 1024, g_W1Bn_H, g_W1Bn_L, 1024,
                      1024, nt, sp, sp * 128, sp * 128 + 128);
        }
        grid_bar(gen);
        for (int g4 = gtid; g4 < 16384; g4 += nthr) {
            int e = g4 * 4;
            int r = e >> 10, n = e & 1023;
            float4 s4 = make_float4(0.f, 0.f, 0.f, 0.f);
#pragma unroll
            for (int sp = 0; sp < 8; sp++) {
                float4 p = __ldcg((const float4*)&g_part[sp * 65536 + e]);
                s4.x += p.x; s4.y += p.y; s4.z += p.z; s4.w += p.w;
            }
            float4 xh = __ldcg((const float4*)&g_xh1[e]);
            float4 bi = *(const float4*)&g_bias[5120 + n];
            float4 z4 = __ldcg((const float4*)&g_z[e]);
            float4 h4 = __ldcg((const float4*)&g_cat[r * 2048 + 1024 + n]);
            float hn[4];
            hn[0] = (1.f - z4.x) * h4.x + z4.x * tanhf(s4.x + xh.x + bi.x);
            hn[1] = (1.f - z4.y) * h4.y + z4.y * tanhf(s4.y + xh.y + bi.y);
            hn[2] = (1.f - z4.z) * h4.z + z4.z * tanhf(s4.z + xh.z + bi.z);
            hn[3] = (1.f - z4.w) * h4.w + z4.w * tanhf(s4.w + xh.w + bi.w);
            *(float4*)&g_cat[r * 2048 + 1024 + n] = make_float4(hn[0], hn[1], hn[2], hn[3]);
            split4(hn, g_catH, g_catL, r * 2048 + 1024 + n);
            split4(hn, g_topH, g_topL, (int)((size_t)(sb + r) * 1024 + n));
        }
        grid_bar(gen);
    }
}

// ---------------- logits GEMM via mma.sync (hi/lo, 3-pass) -------------
__global__ __launch_bounds__(256) void k_logits_mma(const float* __restrict__ bout,
                                                    float* __restrict__ out) {
    __shared__ __align__(16) __nv_bfloat16 sAH[128 * 32];
    __shared__ __align__(16) __nv_bfloat16 sAL[128 * 32];
    __shared__ __align__(16) __nv_bfloat16 sBH[128 * 32];
    __shared__ __align__(16) __nv_bfloat16 sBL[128 * 32];
    const int tid = threadIdx.x, wid = tid >> 5, lane = tid & 31;
    const int m0 = blockIdx.y * 128, n0 = blockIdx.x * 128;
    const int wm = (wid & 1) * 64, wn = (wid >> 1) * 32;
    const uint32_t bAH = s2u(sAH), bAL = s2u(sAL), bBH = s2u(sBH), bBL = s2u(sBL);

    float acc[4][4][4];
#pragma unroll
    for (int i = 0; i < 4; i++)
#pragma unroll
        for (int j = 0; j < 4; j++)
#pragma unroll
            for (int q = 0; q < 4; q++) acc[i][j][q] = 0.f;

    for (int kc = 0; kc < 32; kc++) {
        const int k0 = kc * 32;
#pragma unroll
        for (int h = 0; h < 2; h++) {
            int row = (tid >> 2) + h * 64;
            int g = tid & 3;
            uint32_t off = row * 64 + ((g ^ ((row >> 1) & 3)) << 4);
            size_t goA = (size_t)(m0 + row) * 1024 + k0 + g * 8;
            *(uint4*)((char*)sAH + off) = *(const uint4*)&g_topH[goA];
            *(uint4*)((char*)sAL + off) = *(const uint4*)&g_topL[goA];
            uint4 vh = make_uint4(0, 0, 0, 0), vl = make_uint4(0, 0, 0, 0);
            if (n0 + row < VOCAB) {
                size_t goB = (size_t)(n0 + row) * 1024 + k0 + g * 8;
                vh = *(const uint4*)&g_WoH[goB];
                vl = *(const uint4*)&g_WoL[goB];
            }
            *(uint4*)((char*)sBH + off) = vh;
            *(uint4*)((char*)sBL + off) = vl;
        }
        __syncthreads();
#pragma unroll
        for (int kb = 0; kb < 32; kb += 16) {
            uint32_t aH[4][4], aL[4][4], bH[4][2], bL[4][2];
            int ar = wm + (lane & 15);
            int ag = (kb >> 3) + (lane >> 4);
#pragma unroll
            for (int mf = 0; mf < 4; mf++) {
                int m = ar + mf * 16;
                uint32_t off = m * 64 + ((ag ^ ((m >> 1) & 3)) << 4);
                ldsm4(aH[mf], bAH + off);
                ldsm4(aL[mf], bAL + off);
            }
            int br = wn + (lane & 7);
            int bg = (kb >> 3) + ((lane >> 3) & 1);
#pragma unroll
            for (int nf = 0; nf < 4; nf++) {
                int n = br + nf * 8;
                uint32_t off = n * 64 + ((bg ^ ((n >> 1) & 3)) << 4);
                ldsm2(bH[nf], bBH + off);
                ldsm2(bL[nf], bBL + off);
            }
#pragma unroll
            for (int mf = 0; mf < 4; mf++)
#pragma unroll
                for (int nf = 0; nf < 4; nf++) {
                    mma16816(acc[mf][nf], aH[mf], bH[nf]);
                    mma16816(acc[mf][nf], aH[mf], bL[nf]);
                    mma16816(acc[mf][nf], aL[mf], bH[nf]);
                }
        }
        __syncthreads();
    }

    int r0 = m0 + wm + (lane >> 2);
    int c0 = n0 + wn + (lane & 3) * 2;
#pragma unroll
    for (int mf = 0; mf < 4; mf++)
#pragma unroll
        for (int nf = 0; nf < 4; nf++) {
            int r = r0 + mf * 16, c = c0 + nf * 8;
            if (c < VOCAB) {
                float bx = bout[c], by = bout[c + 1];
                *(float2*)&out[(size_t)r * VOCAB + c] =
                    make_float2(acc[mf][nf][0] + bx, acc[mf][nf][1] + by);
                *(float2*)&out[(size_t)(r + 8) * VOCAB + c] =
                    make_float2(acc[mf][nf][2] + bx, acc[mf][nf][3] + by);
            }
        }
}

// ---------------- final hidden state -----------------------------------
__global__ void k_final(float* __restrict__ out) {
    int idx = blockIdx.x * blockDim.x + threadIdx.x;
    if (idx < 2 * 64 * 1024) {
        int l = idx >> 16;
        int rem = idx & 65535;
        int b = rem >> 10, j = rem & 1023;
        out[(size_t)16384 * VOCAB + idx] = g_cat[b * 2048 + l * 1024 + j];
    }
}

// ---------------- launch ------------------------------------------------
extern "C" void kernel_launch(void* const* d_in, const int* in_sizes, int n_in,
                              void* d_out, int out_size) {
    const int*   inputs = (const int*)d_in[0];
    const float* hidden = (const float*)d_in[1];
    const float* Emb    = (const float*)d_in[2];
    const float* Wr0 = (const float*)d_in[3];  const float* br0 = (const float*)d_in[4];
    const float* Wz0 = (const float*)d_in[5];  const float* bz0 = (const float*)d_in[6];
    const float* Wh0 = (const float*)d_in[7];  const float* bh0 = (const float*)d_in[8];
    const float* Wr1 = (const float*)d_in[9];  const float* br1 = (const float*)d_in[10];
    const float* Wz1 = (const float*)d_in[11]; const float* bz1 = (const float*)d_in[12];
    const float* Wh1 = (const float*)d_in[13]; const float* bh1 = (const float*)d_in[14];
    const float* Wout = (const float*)d_in[15];
    const float* bout = (const float*)d_in[16];
    float* out = (float*)d_out;

    k_prep<<<512, 256>>>(hidden, br0, bz0, bh0, br1, bz1, bh1);
    k_wprep<<<dim3(96, 64, 5), 256>>>(Wr0, Wz0, Wh0, Wr1, Wz1, Wh1);
    k_esplit<<<20000, 256>>>(Emb);
    k_wsplit<<<dim3(313, 32), 256>>>(Wout);
    k_embed_mma<<<dim3(24, 128), 256>>>(inputs);
    k_rec_persist<<<148, 256>>>();
    k_logits_mma<<<dim3(79, 128), 256>>>(bout, out);
    k_final<<<512, 256>>>(out);
}